// round 11
// baseline (speedup 1.0000x reference)
#include <cuda_runtime.h>
#include <cuda_bf16.h>
#include <cstdint>
#include <cstddef>

// Problem constants (fixed by setup_inputs)
#define BATCH 4
#define SEQ   1024
#define DIM   1152
#define HEADS 16
#define HDIM  72
#define ROWS  (BATCH*SEQ)          // 4096
#define QKVN  (3*DIM)              // 3456
#define TOTAL_ELEMS 4718592.0f     // B*H*N*hd for loss mean
#define QSCALE 0.11785113f         // 72^-0.5

// Scratch (static device allocation — allowed). All bf16 hi/lo pairs.
__device__ __align__(16) __nv_bfloat16 g_xh [(size_t)ROWS * DIM];
__device__ __align__(16) __nv_bfloat16 g_xl [(size_t)ROWS * DIM];
__device__ __align__(16) __nv_bfloat16 g_wqh[(size_t)QKVN * DIM];
__device__ __align__(16) __nv_bfloat16 g_wql[(size_t)QKVN * DIM];
__device__ __align__(16) __nv_bfloat16 g_wph[(size_t)DIM * DIM];
__device__ __align__(16) __nv_bfloat16 g_wpl[(size_t)DIM * DIM];
// head-major [bh][seq][72] bf16 Q/K/V (hi/lo), written by QKV GEMM epilogue
__device__ __align__(16) __nv_bfloat16 g_qh [(size_t)ROWS * DIM];
__device__ __align__(16) __nv_bfloat16 g_ql [(size_t)ROWS * DIM];
__device__ __align__(16) __nv_bfloat16 g_kh [(size_t)ROWS * DIM];
__device__ __align__(16) __nv_bfloat16 g_kl [(size_t)ROWS * DIM];
__device__ __align__(16) __nv_bfloat16 g_vh [(size_t)ROWS * DIM];
__device__ __align__(16) __nv_bfloat16 g_vl [(size_t)ROWS * DIM];
// encoder K/V pre-split (same [bh][seq][72] layout as the fp32 inputs)
__device__ __align__(16) __nv_bfloat16 g_ekh[(size_t)ROWS * DIM];
__device__ __align__(16) __nv_bfloat16 g_ekl[(size_t)ROWS * DIM];
__device__ __align__(16) __nv_bfloat16 g_evh[(size_t)ROWS * DIM];
__device__ __align__(16) __nv_bfloat16 g_evl[(size_t)ROWS * DIM];
// attention output (hi/lo) -> proj GEMM input
__device__ __align__(16) __nv_bfloat16 g_oh [(size_t)ROWS * DIM];
__device__ __align__(16) __nv_bfloat16 g_ol [(size_t)ROWS * DIM];

extern __shared__ char dynsm[];

// ---------------------------------------------------------------------------
// helpers
// ---------------------------------------------------------------------------
__device__ __forceinline__ void cp16(uint32_t dst, const void* src) {
    asm volatile("cp.async.cg.shared.global [%0], [%1], 16;" :: "r"(dst), "l"(src));
}
__device__ __forceinline__ void mma_bf16(float* d, const uint32_t* a, const uint32_t* b) {
    asm volatile(
        "mma.sync.aligned.m16n8k16.row.col.f32.bf16.bf16.f32 "
        "{%0,%1,%2,%3}, {%4,%5,%6,%7}, {%8,%9}, {%0,%1,%2,%3};"
        : "+f"(d[0]), "+f"(d[1]), "+f"(d[2]), "+f"(d[3])
        : "r"(a[0]), "r"(a[1]), "r"(a[2]), "r"(a[3]), "r"(b[0]), "r"(b[1]));
}
__device__ __forceinline__ void ldsm_x2_trans(uint32_t& r0, uint32_t& r1, uint32_t saddr) {
    asm volatile("ldmatrix.sync.aligned.m8n8.x2.trans.shared.b16 {%0,%1}, [%2];"
                 : "=r"(r0), "=r"(r1) : "r"(saddr));
}
__device__ __forceinline__ void split2(float x, float y, uint32_t& h, uint32_t& l) {
    __nv_bfloat16 h0 = __float2bfloat16(x);
    __nv_bfloat16 h1 = __float2bfloat16(y);
    __nv_bfloat16 l0 = __float2bfloat16(x - __bfloat162float(h0));
    __nv_bfloat16 l1 = __float2bfloat16(y - __bfloat162float(h1));
    __nv_bfloat162 hh; hh.x = h0; hh.y = h1;
    __nv_bfloat162 ll; ll.x = l0; ll.y = l1;
    h = *(uint32_t*)&hh;
    l = *(uint32_t*)&ll;
}

// ---------------------------------------------------------------------------
// fp32 -> bf16 (hi, lo) split kernel
// ---------------------------------------------------------------------------
__global__ __launch_bounds__(256)
void split_bf16_kernel(const float* __restrict__ src,
                       __nv_bfloat16* __restrict__ hi,
                       __nv_bfloat16* __restrict__ lo, int n4)
{
    int i = blockIdx.x * 256 + threadIdx.x;
    if (i >= n4) return;
    float4 v = ((const float4*)src)[i];
    uint32_t h0, l0, h1, l1;
    split2(v.x, v.y, h0, l0);
    split2(v.z, v.w, h1, l1);
    ((uint32_t*)hi)[2 * i]     = h0;
    ((uint32_t*)hi)[2 * i + 1] = h1;
    ((uint32_t*)lo)[2 * i]     = l0;
    ((uint32_t*)lo)[2 * i + 1] = l1;
}

// ---------------------------------------------------------------------------
// Tensor-core GEMM (3-term bf16 split). EPI=0: fp32 C (+bias). EPI=1: QKV
// epilogue — bias, head-major remap, q-scaling, bf16 hi/lo split stores.
// ---------------------------------------------------------------------------
#define GM_SMEM_BYTES 81920

template<int EPI>
__global__ __launch_bounds__(256, 2)
void gemm_mma_kernel(const __nv_bfloat16* __restrict__ Ah, const __nv_bfloat16* __restrict__ Al,
                     const __nv_bfloat16* __restrict__ Bh, const __nv_bfloat16* __restrict__ Bl,
                     const float* __restrict__ bias, float* __restrict__ C,
                     int M, int N, int K)
{
    __nv_bfloat16* sb = (__nv_bfloat16*)dynsm;
    const uint32_t sb32 = (uint32_t)__cvta_generic_to_shared(sb);

    const int tid  = threadIdx.x;
    const int warp = tid >> 5, lane = tid & 31;
    const int wm = warp >> 2, wn = warp & 3;
    const int gr = lane >> 2, c4 = lane & 3;
    const int m0 = blockIdx.y * 128, n0 = blockIdx.x * 128;

    const int l_row0 = tid >> 2,            l_cb0 = (tid & 3) << 3;
    const int l_row1 = (tid + 256) >> 2,    l_cb1 = ((tid + 256) & 3) << 3;

    float acc[4][4][4];
#pragma unroll
    for (int i = 0; i < 4; i++)
#pragma unroll
        for (int j = 0; j < 4; j++)
#pragma unroll
            for (int r = 0; r < 4; r++) acc[i][j][r] = 0.f;

    const int nkt = K >> 5;

    auto load_tile = [&](int stage, int kt) {
        const int k0 = kt << 5;
        const uint32_t st = sb32 + stage * 40960u;
        cp16(st + (uint32_t)(l_row0 * 80 + l_cb0 * 2),
             Ah + (size_t)(m0 + l_row0) * K + k0 + l_cb0);
        cp16(st + (uint32_t)(l_row1 * 80 + l_cb1 * 2),
             Ah + (size_t)(m0 + l_row1) * K + k0 + l_cb1);
        cp16(st + 10240u + (uint32_t)(l_row0 * 80 + l_cb0 * 2),
             Al + (size_t)(m0 + l_row0) * K + k0 + l_cb0);
        cp16(st + 10240u + (uint32_t)(l_row1 * 80 + l_cb1 * 2),
             Al + (size_t)(m0 + l_row1) * K + k0 + l_cb1);
        cp16(st + 20480u + (uint32_t)(l_row0 * 80 + l_cb0 * 2),
             Bh + (size_t)(n0 + l_row0) * K + k0 + l_cb0);
        cp16(st + 20480u + (uint32_t)(l_row1 * 80 + l_cb1 * 2),
             Bh + (size_t)(n0 + l_row1) * K + k0 + l_cb1);
        cp16(st + 30720u + (uint32_t)(l_row0 * 80 + l_cb0 * 2),
             Bl + (size_t)(n0 + l_row0) * K + k0 + l_cb0);
        cp16(st + 30720u + (uint32_t)(l_row1 * 80 + l_cb1 * 2),
             Bl + (size_t)(n0 + l_row1) * K + k0 + l_cb1);
        asm volatile("cp.async.commit_group;");
    };

    load_tile(0, 0);
    load_tile(1, 1);

    for (int kt = 0; kt < nkt; kt++) {
        if (kt + 1 < nkt) asm volatile("cp.async.wait_group 1;");
        else              asm volatile("cp.async.wait_group 0;");
        __syncthreads();

        const __nv_bfloat16* sAh = sb + (kt & 1) * 20480;
        const __nv_bfloat16* sAl = sAh + 5120;
        const __nv_bfloat16* sBh = sAh + 10240;
        const __nv_bfloat16* sBl = sAh + 15360;

#pragma unroll
        for (int ks = 0; ks < 2; ks++) {
            const int kb = ks * 16 + 2 * c4;
            uint32_t bh[4][2], bl[4][2];
#pragma unroll
            for (int j = 0; j < 4; j++) {
                const int nrow = wn * 32 + j * 8 + gr;
                const __nv_bfloat16* p = sBh + nrow * 40 + kb;
                const __nv_bfloat16* q = sBl + nrow * 40 + kb;
                bh[j][0] = *(const uint32_t*)p;
                bh[j][1] = *(const uint32_t*)(p + 8);
                bl[j][0] = *(const uint32_t*)q;
                bl[j][1] = *(const uint32_t*)(q + 8);
            }
#pragma unroll
            for (int i = 0; i < 4; i++) {
                const int ar = wm * 64 + i * 16 + gr;
                const __nv_bfloat16* p = sAh + ar * 40 + kb;
                const __nv_bfloat16* q = sAl + ar * 40 + kb;
                uint32_t ah[4], al[4];
                ah[0] = *(const uint32_t*)p;
                ah[1] = *(const uint32_t*)(p + 320);
                ah[2] = *(const uint32_t*)(p + 8);
                ah[3] = *(const uint32_t*)(p + 328);
                al[0] = *(const uint32_t*)q;
                al[1] = *(const uint32_t*)(q + 320);
                al[2] = *(const uint32_t*)(q + 8);
                al[3] = *(const uint32_t*)(q + 328);
#pragma unroll
                for (int j = 0; j < 4; j++) {
                    mma_bf16(acc[i][j], ah, bh[j]);
                    mma_bf16(acc[i][j], ah, bl[j]);
                    mma_bf16(acc[i][j], al, bh[j]);
                }
            }
        }
        __syncthreads();
        if (kt + 2 < nkt) load_tile(kt & 1, kt + 2);
    }

#pragma unroll
    for (int j = 0; j < 4; j++) {
        const int gn = n0 + wn * 32 + j * 8 + 2 * c4;
        const float b0 = bias[gn], b1 = bias[gn + 1];
        if (EPI == 0) {
#pragma unroll
            for (int i = 0; i < 4; i++) {
                const int gm = m0 + wm * 64 + i * 16 + gr;
                float2 w0, w1;
                w0.x = acc[i][j][0] + b0; w0.y = acc[i][j][1] + b1;
                w1.x = acc[i][j][2] + b0; w1.y = acc[i][j][3] + b1;
                *(float2*)&C[(size_t)gm * N + gn] = w0;
                *(float2*)&C[(size_t)(gm + 8) * N + gn] = w1;
            }
        } else {
            // QKV epilogue: part (q/k/v), head-major [bh][seq][72] bf16 hi/lo
            const int part = gn / DIM;
            const int rem  = gn - part * DIM;
            const int hh   = rem / HDIM;
            const int dd   = rem - hh * HDIM;          // even
            uint32_t* dsth;
            uint32_t* dstl;
            float sc = 1.f;
            if (part == 0)      { dsth = (uint32_t*)g_qh; dstl = (uint32_t*)g_ql; sc = QSCALE; }
            else if (part == 1) { dsth = (uint32_t*)g_kh; dstl = (uint32_t*)g_kl; }
            else                { dsth = (uint32_t*)g_vh; dstl = (uint32_t*)g_vl; }
#pragma unroll
            for (int i = 0; i < 4; i++) {
                const int gm = m0 + wm * 64 + i * 16 + gr;
                const int b_ = gm >> 10, seq = gm & 1023;
                const size_t idx = (((size_t)(b_ * HEADS + hh) << 10) + seq) * 36 + (dd >> 1);
                uint32_t h_, l_;
                split2((acc[i][j][0] + b0) * sc, (acc[i][j][1] + b1) * sc, h_, l_);
                dsth[idx] = h_; dstl[idx] = l_;
                split2((acc[i][j][2] + b0) * sc, (acc[i][j][3] + b1) * sc, h_, l_);
                dsth[idx + 8 * 36] = h_; dstl[idx + 8 * 36] = l_;
            }
        }
    }
}

// ---------------------------------------------------------------------------
// Attention v5: 128-query tiles, 512 threads (16 warps), tensor-core
// scores/PV (3-term bf16), pre-split bf16 inputs, cp.async double-buffered K/V.
//
// smem (bytes):
//   sQh @0, sQl @22528                (each [128][88] bf16 = 22528)
//   KV  @45056: 2 bufs x {Kh,Kl,Vh,Vl} (each [64][88] bf16 = 11264; buf=45056)
//   sPs @135168  fp32 [128][68]  (34816)
//   sPh @169984, sPl @188416  bf16 [128][72] (18432 each)
//   sRow @206848 fp32 [128]  -> total 207360
// ---------------------------------------------------------------------------
#define AT_SMEM_BYTES 207360

__global__ __launch_bounds__(512)
void attn_kernel(float* __restrict__ loss_out)
{
    __nv_bfloat16* smbf = (__nv_bfloat16*)dynsm;
    __nv_bfloat16* sQh = smbf;
    __nv_bfloat16* sQl = smbf + 11264;
    float*         sPs = (float*)(dynsm + 135168);
    __nv_bfloat16* sPh = (__nv_bfloat16*)(dynsm + 169984);
    __nv_bfloat16* sPl = (__nv_bfloat16*)(dynsm + 188416);
    float*         sRow = (float*)(dynsm + 206848);

    const uint32_t smu   = (uint32_t)__cvta_generic_to_shared(smbf);
    const uint32_t kvb32 = smu + 45056u;

    const int tid  = threadIdx.x;
    const int warp = tid >> 5, lane = tid & 31;
    const int gr = lane >> 2, c4 = lane & 3;
    const int wm  = warp >> 2, wn  = warp & 3;   // score grid 4m x 4n
    const int wm2 = warp >> 1, wn2 = warp & 1;   // PV grid 8m x 2n
    const int r_row = tid >> 2, r_sub = tid & 3; // softmax role (128 rows)

    const int bh = blockIdx.y, b = bh >> 4, h = bh & 15;
    const int n0 = blockIdx.x * 128;

    // ---- K/V tile prefetch (64 keys; 4 arrays x 64 rows x 9 chunks = 2304) ----
    auto prefetch = [&](int t, int buf) {
        const int kt = t & 15;
        const __nv_bfloat16* s0 = (t < 16) ? g_kh : g_ekh;
        const __nv_bfloat16* s1 = (t < 16) ? g_kl : g_ekl;
        const __nv_bfloat16* s2 = (t < 16) ? g_vh : g_evh;
        const __nv_bfloat16* s3 = (t < 16) ? g_vl : g_evl;
        const size_t toff = (((size_t)bh << 10) + kt * 64) * HDIM;
#pragma unroll
        for (int r = 0; r < 5; r++) {
            int e = tid + r * 512;
            if (e < 2304) {
                int arr = e / 576, rem = e - arr * 576;
                int row = rem / 9,  ch  = rem - row * 9;
                const __nv_bfloat16* src =
                    (arr == 0 ? s0 : arr == 1 ? s1 : arr == 2 ? s2 : s3)
                    + toff + row * HDIM + ch * 8;
                cp16(kvb32 + buf * 45056u + arr * 11264u
                           + (uint32_t)(row * 176 + ch * 16), src);
            }
        }
        asm volatile("cp.async.commit_group;");
    };
    prefetch(0, 0);

    // ---- zero pads (cols 72..87): sQh/sQl (128 rows) + 8 KV arrays (64 rows) ----
    for (int i = tid; i < 2048; i += 512) {           // Q arrays
        int arr = i >> 10, rem = i & 1023;
        int row = rem >> 3, cp = rem & 7;
        *(uint32_t*)(smbf + arr * 11264 + row * 88 + 72 + 2 * cp) = 0;
    }
    for (int i = tid; i < 4096; i += 512) {           // KV arrays
        int arr = i >> 9, rem = i & 511;
        int row = rem >> 3, cp = rem & 7;
        *(uint32_t*)(smbf + 22528 + arr * 5632 + row * 88 + 72 + 2 * cp) = 0;
    }

    // ---- load Q tile (bf16 hi/lo, pre-scaled): 128 rows x 36 chunks ----
    {
        const uint32_t* qh = (const uint32_t*)g_qh;
        const uint32_t* ql = (const uint32_t*)g_ql;
        const size_t qoff = (((size_t)bh << 10) + n0) * 36;
#pragma unroll
        for (int r = 0; r < 9; r++) {
            int e = tid + r * 512;                    // 0..4607
            int row = e / 36, ch = e - row * 36;
            size_t gi = qoff + row * 36 + ch;
            *(uint32_t*)(sQh + row * 88 + ch * 2) = qh[gi];
            *(uint32_t*)(sQl + row * 88 + ch * 2) = ql[gi];
        }
    }

    float xo[20];
    float lsum = 0.f;
    float m_ = -1e30f, l_ = 0.f;
    float oacc[5][4];
#pragma unroll
    for (int j = 0; j < 5; j++)
#pragma unroll
        for (int r = 0; r < 4; r++) oacc[j][r] = 0.f;

#pragma unroll 1
    for (int t = 0; t < 32; t++) {
        const int buf = t & 1;

        asm volatile("cp.async.wait_group 0;");
        __syncthreads();
        if (t + 1 < 32) prefetch(t + 1, buf ^ 1);

        const __nv_bfloat16* sKh = smbf + 22528 + buf * 22528;
        const __nv_bfloat16* sKl = sKh + 5632;
        const uint32_t vh_base = kvb32 + buf * 45056u + 22528u;

        // ---- scores: S = Q K^T via MMA (3 terms); warp = 32q x 16k ----
        {
            float sacc[2][2][4];
#pragma unroll
            for (int i = 0; i < 2; i++)
#pragma unroll
                for (int j = 0; j < 2; j++)
#pragma unroll
                    for (int r = 0; r < 4; r++) sacc[i][j][r] = 0.f;

#pragma unroll
            for (int ks = 0; ks < 5; ks++) {
                const int kb = ks * 16 + 2 * c4;
                uint32_t bh2[2][2], bl2[2][2];
#pragma unroll
                for (int j = 0; j < 2; j++) {
                    const int nr = wn * 16 + j * 8 + gr;
                    const __nv_bfloat16* p = sKh + nr * 88 + kb;
                    const __nv_bfloat16* q = sKl + nr * 88 + kb;
                    bh2[j][0] = *(const uint32_t*)p;
                    bh2[j][1] = *(const uint32_t*)(p + 8);
                    bl2[j][0] = *(const uint32_t*)q;
                    bl2[j][1] = *(const uint32_t*)(q + 8);
                }
#pragma unroll
                for (int i = 0; i < 2; i++) {
                    const int ar = wm * 32 + i * 16 + gr;
                    const __nv_bfloat16* p = sQh + ar * 88 + kb;
                    const __nv_bfloat16* q = sQl + ar * 88 + kb;
                    uint32_t ah[4], al[4];
                    ah[0] = *(const uint32_t*)p;
                    ah[1] = *(const uint32_t*)(p + 8 * 88);
                    ah[2] = *(const uint32_t*)(p + 8);
                    ah[3] = *(const uint32_t*)(p + 8 * 88 + 8);
                    al[0] = *(const uint32_t*)q;
                    al[1] = *(const uint32_t*)(q + 8 * 88);
                    al[2] = *(const uint32_t*)(q + 8);
                    al[3] = *(const uint32_t*)(q + 8 * 88 + 8);
#pragma unroll
                    for (int j = 0; j < 2; j++) {
                        mma_bf16(sacc[i][j], ah, bh2[j]);
                        mma_bf16(sacc[i][j], ah, bl2[j]);
                        mma_bf16(sacc[i][j], al, bh2[j]);
                    }
                }
            }
#pragma unroll
            for (int i = 0; i < 2; i++)
#pragma unroll
                for (int j = 0; j < 2; j++) {
                    const int row = wm * 32 + i * 16 + gr;
                    const int col = wn * 16 + j * 8 + 2 * c4;
                    *(float2*)&sPs[row * 68 + col] =
                        make_float2(sacc[i][j][0], sacc[i][j][1]);
                    *(float2*)&sPs[(row + 8) * 68 + col] =
                        make_float2(sacc[i][j][2], sacc[i][j][3]);
                }
        }
        __syncthreads();

        // ---- softmax (row r_row, cols r_sub*16..+15), emit Ph/Pl bf16 ----
        {
            const float* prow = sPs + r_row * 68 + r_sub * 16;
            float4 t0 = *(const float4*)(prow + 0);
            float4 t1 = *(const float4*)(prow + 4);
            float4 t2 = *(const float4*)(prow + 8);
            float4 t3 = *(const float4*)(prow + 12);
            float tmax = fmaxf(fmaxf(fmaxf(t0.x,t0.y),fmaxf(t0.z,t0.w)),
                               fmaxf(fmaxf(t1.x,t1.y),fmaxf(t1.z,t1.w)));
            tmax = fmaxf(tmax, fmaxf(fmaxf(t2.x,t2.y),fmaxf(t2.z,t2.w)));
            tmax = fmaxf(tmax, fmaxf(fmaxf(t3.x,t3.y),fmaxf(t3.z,t3.w)));
            tmax = fmaxf(tmax, __shfl_xor_sync(0xffffffffu, tmax, 1));
            tmax = fmaxf(tmax, __shfl_xor_sync(0xffffffffu, tmax, 2));
            float nm = fmaxf(m_, tmax);
            float corr = __expf(m_ - nm);
            t0.x=__expf(t0.x-nm); t0.y=__expf(t0.y-nm); t0.z=__expf(t0.z-nm); t0.w=__expf(t0.w-nm);
            t1.x=__expf(t1.x-nm); t1.y=__expf(t1.y-nm); t1.z=__expf(t1.z-nm); t1.w=__expf(t1.w-nm);
            t2.x=__expf(t2.x-nm); t2.y=__expf(t2.y-nm); t2.z=__expf(t2.z-nm); t2.w=__expf(t2.w-nm);
            t3.x=__expf(t3.x-nm); t3.y=__expf(t3.y-nm); t3.z=__expf(t3.z-nm); t3.w=__expf(t3.w-nm);
            float ps = (t0.x+t0.y+t0.z+t0.w) + (t1.x+t1.y+t1.z+t1.w)
                     + (t2.x+t2.y+t2.z+t2.w) + (t3.x+t3.y+t3.z+t3.w);
            ps += __shfl_xor_sync(0xffffffffu, ps, 1);
            ps += __shfl_xor_sync(0xffffffffu, ps, 2);
            l_ = l_ * corr + ps;
            m_ = nm;

            __nv_bfloat16* ph = sPh + r_row * 72 + r_sub * 16;
            __nv_bfloat16* pl = sPl + r_row * 72 + r_sub * 16;
            uint32_t hh, ll;
            split2(t0.x, t0.y, hh, ll); *(uint32_t*)(ph+ 0)=hh; *(uint32_t*)(pl+ 0)=ll;
            split2(t0.z, t0.w, hh, ll); *(uint32_t*)(ph+ 2)=hh; *(uint32_t*)(pl+ 2)=ll;
            split2(t1.x, t1.y, hh, ll); *(uint32_t*)(ph+ 4)=hh; *(uint32_t*)(pl+ 4)=ll;
            split2(t1.z, t1.w, hh, ll); *(uint32_t*)(ph+ 6)=hh; *(uint32_t*)(pl+ 6)=ll;
            split2(t2.x, t2.y, hh, ll); *(uint32_t*)(ph+ 8)=hh; *(uint32_t*)(pl+ 8)=ll;
            split2(t2.z, t2.w, hh, ll); *(uint32_t*)(ph+10)=hh; *(uint32_t*)(pl+10)=ll;
            split2(t3.x, t3.y, hh, ll); *(uint32_t*)(ph+12)=hh; *(uint32_t*)(pl+12)=ll;
            split2(t3.z, t3.w, hh, ll); *(uint32_t*)(ph+14)=hh; *(uint32_t*)(pl+14)=ll;
            if (r_sub == 0) sRow[r_row] = corr;
        }
        __syncthreads();

        // ---- PV: O = corr*O + P V via MMA (3 terms); warp = 16q x 40d ----
        {
            const float cr0 = sRow[wm2 * 16 + gr];
            const float cr1 = sRow[wm2 * 16 + gr + 8];
#pragma unroll
            for (int j = 0; j < 5; j++) {
                oacc[j][0] *= cr0; oacc[j][1] *= cr0;
                oacc[j][2] *= cr1; oacc[j][3] *= cr1;
            }
#pragma unroll
            for (int ks = 0; ks < 4; ks++) {
                const __nv_bfloat16* p = sPh + (wm2 * 16 + gr) * 72 + ks * 16 + 2 * c4;
                const __nv_bfloat16* q = sPl + (wm2 * 16 + gr) * 72 + ks * 16 + 2 * c4;
                uint32_t ph[4], pl[4];
                ph[0] = *(const uint32_t*)p;
                ph[1] = *(const uint32_t*)(p + 8 * 72);
                ph[2] = *(const uint32_t*)(p + 8);
                ph[3] = *(const uint32_t*)(p + 8 * 72 + 8);
                pl[0] = *(const uint32_t*)q;
                pl[1] = *(const uint32_t*)(q + 8 * 72);
                pl[2] = *(const uint32_t*)(q + 8);
                pl[3] = *(const uint32_t*)(q + 8 * 72 + 8);
                const uint32_t rowb = vh_base +
                    (uint32_t)(((ks * 16 + (lane & 15)) * 88) * 2);
#pragma unroll
                for (int j = 0; j < 5; j++) {
                    const uint32_t va = rowb + (uint32_t)((wn2 * 40 + j * 8) * 2);
                    uint32_t vh2[2], vl2[2];
                    ldsm_x2_trans(vh2[0], vh2[1], va);
                    ldsm_x2_trans(vl2[0], vl2[1], va + 11264u);
                    mma_bf16(oacc[j], ph, vh2);
                    mma_bf16(oacc[j], ph, vl2);
                    mma_bf16(oacc[j], pl, vh2);
                }
            }
        }

        // ---- pass epilogues at t==15 (own) and t==31 (encoder) ----
        if (t == 15 || t == 31) {
            __syncthreads();
            if (r_sub == 0) sRow[r_row] = 1.0f / l_;
            __syncthreads();
            const float i0 = sRow[wm2 * 16 + gr];
            const float i1 = sRow[wm2 * 16 + gr + 8];
            if (t == 15) {
                const int q0 = n0 + wm2 * 16 + gr;
                uint32_t* dh = (uint32_t*)g_oh;
                uint32_t* dl = (uint32_t*)g_ol;
#pragma unroll
                for (int j = 0; j < 5; j++) {
                    const int dim = wn2 * 40 + j * 8 + 2 * c4;
                    xo[j*4+0] = oacc[j][0] * i0; xo[j*4+1] = oacc[j][1] * i0;
                    xo[j*4+2] = oacc[j][2] * i1; xo[j*4+3] = oacc[j][3] * i1;
                    if (dim < 72) {
                        const size_t i0x = (((size_t)(b * SEQ + q0)) * DIM
                                            + h * HDIM + dim) >> 1;
                        const size_t i1x = (((size_t)(b * SEQ + q0 + 8)) * DIM
                                            + h * HDIM + dim) >> 1;
                        uint32_t hh, ll;
                        split2(xo[j*4+0], xo[j*4+1], hh, ll);
                        dh[i0x] = hh; dl[i0x] = ll;
                        split2(xo[j*4+2], xo[j*4+3], hh, ll);
                        dh[i1x] = hh; dl[i1x] = ll;
                    }
                }
                m_ = -1e30f; l_ = 0.f;
#pragma unroll
                for (int j = 0; j < 5; j++)
#pragma unroll
                    for (int r = 0; r < 4; r++) oacc[j][r] = 0.f;
            } else {
#pragma unroll
                for (int j = 0; j < 5; j++) {
                    const int dim = wn2 * 40 + j * 8 + 2 * c4;
                    if (dim < 72) {
                        float e0 = xo[j*4+0] - oacc[j][0] * i0;
                        float e1 = xo[j*4+1] - oacc[j][1] * i0;
                        float e2 = xo[j*4+2] - oacc[j][2] * i1;
                        float e3 = xo[j*4+3] - oacc[j][3] * i1;
                        lsum += e0*e0 + e1*e1 + e2*e2 + e3*e3;
                    }
                }
            }
        }
    }

    // loss reduction
    lsum *= (1.0f / TOTAL_ELEMS);
#pragma unroll
    for (int o = 16; o > 0; o >>= 1)
        lsum += __shfl_down_sync(0xffffffffu, lsum, o);
    if (lane == 0) atomicAdd(loss_out, lsum);
}

// ---------------------------------------------------------------------------
extern "C" void kernel_launch(void* const* d_in, const int* in_sizes, int n_in,
                              void* d_out, int out_size)
{
    const float* x      = (const float*)d_in[0];
    const float* enc_k  = (const float*)d_in[1];
    const float* enc_v  = (const float*)d_in[2];
    const float* qkv_w  = (const float*)d_in[3];
    const float* qkv_b  = (const float*)d_in[4];
    const float* proj_w = (const float*)d_in[5];
    const float* proj_b = (const float*)d_in[6];
    float* out = (float*)d_out;
    float* loss_ptr = out + (out_size - 1);

    __nv_bfloat16 *xh, *xl, *wqh, *wql, *wph, *wpl, *oh, *ol;
    __nv_bfloat16 *ekh, *ekl, *evh, *evl;
    cudaGetSymbolAddress((void**)&xh,  g_xh);   cudaGetSymbolAddress((void**)&xl,  g_xl);
    cudaGetSymbolAddress((void**)&wqh, g_wqh);  cudaGetSymbolAddress((void**)&wql, g_wql);
    cudaGetSymbolAddress((void**)&wph, g_wph);  cudaGetSymbolAddress((void**)&wpl, g_wpl);
    cudaGetSymbolAddress((void**)&oh,  g_oh);   cudaGetSymbolAddress((void**)&ol,  g_ol);
    cudaGetSymbolAddress((void**)&ekh, g_ekh);  cudaGetSymbolAddress((void**)&ekl, g_ekl);
    cudaGetSymbolAddress((void**)&evh, g_evh);  cudaGetSymbolAddress((void**)&evl, g_evl);

    static bool attr_set = false;
    if (!attr_set) {
        cudaFuncSetAttribute(attn_kernel,
                             cudaFuncAttributeMaxDynamicSharedMemorySize, AT_SMEM_BYTES);
        cudaFuncSetAttribute(gemm_mma_kernel<0>,
                             cudaFuncAttributeMaxDynamicSharedMemorySize, GM_SMEM_BYTES);
        cudaFuncSetAttribute(gemm_mma_kernel<1>,
                             cudaFuncAttributeMaxDynamicSharedMemorySize, GM_SMEM_BYTES);
        attr_set = true;
    }

    cudaMemsetAsync(loss_ptr, 0, sizeof(float));

    // 0) fp32 -> bf16 hi/lo splits (GEMM inputs + encoder K/V)
    {
        int n4x = (ROWS * DIM) / 4;
        int n4q = (QKVN * DIM) / 4;
        int n4p = (DIM * DIM) / 4;
        split_bf16_kernel<<<(n4x + 255) / 256, 256>>>(x,      xh,  xl,  n4x);
        split_bf16_kernel<<<(n4q + 255) / 256, 256>>>(qkv_w,  wqh, wql, n4q);
        split_bf16_kernel<<<(n4p + 255) / 256, 256>>>(proj_w, wph, wpl, n4p);
        split_bf16_kernel<<<(n4x + 255) / 256, 256>>>(enc_k,  ekh, ekl, n4x);
        split_bf16_kernel<<<(n4x + 255) / 256, 256>>>(enc_v,  evh, evl, n4x);
    }

    // 1) QKV GEMM (tensor cores) -> head-major bf16 hi/lo Q(scaled)/K/V
    gemm_mma_kernel<1><<<dim3(QKVN / 128, ROWS / 128), 256, GM_SMEM_BYTES>>>(
        xh, xl, wqh, wql, qkv_b, nullptr, ROWS, QKVN, DIM);

    // 2) Dual attention + loss (tensor cores) -> g_oh/g_ol + loss scalar
    attn_kernel<<<dim3(SEQ / 128, BATCH * HEADS), 512, AT_SMEM_BYTES>>>(loss_ptr);

    // 3) proj GEMM (tensor cores) -> out
    gemm_mma_kernel<0><<<dim3(DIM / 128, ROWS / 128), 256, GM_SMEM_BYTES>>>(
        oh, ol, wph, wpl, proj_b, out, ROWS, DIM, DIM);
}

// round 12
// speedup vs baseline: 1.1775x; 1.1775x over previous
#include <cuda_runtime.h>
#include <cuda_bf16.h>
#include <cstdint>
#include <cstddef>

// Problem constants (fixed by setup_inputs)
#define BATCH 4
#define SEQ   1024
#define DIM   1152
#define HEADS 16
#define HDIM  72
#define ROWS  (BATCH*SEQ)          // 4096
#define QKVN  (3*DIM)              // 3456
#define TOTAL_ELEMS 4718592.0f     // B*H*N*hd for loss mean
#define QSCALE 0.11785113f         // 72^-0.5

// Scratch (static device allocation — allowed). All bf16 hi/lo pairs.
__device__ __align__(16) __nv_bfloat16 g_xh [(size_t)ROWS * DIM];
__device__ __align__(16) __nv_bfloat16 g_xl [(size_t)ROWS * DIM];
__device__ __align__(16) __nv_bfloat16 g_wqh[(size_t)QKVN * DIM];
__device__ __align__(16) __nv_bfloat16 g_wql[(size_t)QKVN * DIM];
__device__ __align__(16) __nv_bfloat16 g_wph[(size_t)DIM * DIM];
__device__ __align__(16) __nv_bfloat16 g_wpl[(size_t)DIM * DIM];
// head-major [bh][seq][72] bf16 Q/K/V (hi/lo), written by QKV GEMM epilogue
__device__ __align__(16) __nv_bfloat16 g_qh [(size_t)ROWS * DIM];
__device__ __align__(16) __nv_bfloat16 g_ql [(size_t)ROWS * DIM];
__device__ __align__(16) __nv_bfloat16 g_kh [(size_t)ROWS * DIM];
__device__ __align__(16) __nv_bfloat16 g_kl [(size_t)ROWS * DIM];
__device__ __align__(16) __nv_bfloat16 g_vh [(size_t)ROWS * DIM];
__device__ __align__(16) __nv_bfloat16 g_vl [(size_t)ROWS * DIM];
// encoder K/V pre-split (same [bh][seq][72] layout as the fp32 inputs)
__device__ __align__(16) __nv_bfloat16 g_ekh[(size_t)ROWS * DIM];
__device__ __align__(16) __nv_bfloat16 g_ekl[(size_t)ROWS * DIM];
__device__ __align__(16) __nv_bfloat16 g_evh[(size_t)ROWS * DIM];
__device__ __align__(16) __nv_bfloat16 g_evl[(size_t)ROWS * DIM];
// attention output (hi/lo) -> proj GEMM input
__device__ __align__(16) __nv_bfloat16 g_oh [(size_t)ROWS * DIM];
__device__ __align__(16) __nv_bfloat16 g_ol [(size_t)ROWS * DIM];

extern __shared__ char dynsm[];

// ---------------------------------------------------------------------------
// helpers
// ---------------------------------------------------------------------------
__device__ __forceinline__ void cp16(uint32_t dst, const void* src) {
    asm volatile("cp.async.cg.shared.global [%0], [%1], 16;" :: "r"(dst), "l"(src));
}
__device__ __forceinline__ void mma_bf16(float* d, const uint32_t* a, const uint32_t* b) {
    asm volatile(
        "mma.sync.aligned.m16n8k16.row.col.f32.bf16.bf16.f32 "
        "{%0,%1,%2,%3}, {%4,%5,%6,%7}, {%8,%9}, {%0,%1,%2,%3};"
        : "+f"(d[0]), "+f"(d[1]), "+f"(d[2]), "+f"(d[3])
        : "r"(a[0]), "r"(a[1]), "r"(a[2]), "r"(a[3]), "r"(b[0]), "r"(b[1]));
}
__device__ __forceinline__ void ldsm_x2_trans(uint32_t& r0, uint32_t& r1, uint32_t saddr) {
    asm volatile("ldmatrix.sync.aligned.m8n8.x2.trans.shared.b16 {%0,%1}, [%2];"
                 : "=r"(r0), "=r"(r1) : "r"(saddr));
}
__device__ __forceinline__ void split2(float x, float y, uint32_t& h, uint32_t& l) {
    __nv_bfloat16 h0 = __float2bfloat16(x);
    __nv_bfloat16 h1 = __float2bfloat16(y);
    __nv_bfloat16 l0 = __float2bfloat16(x - __bfloat162float(h0));
    __nv_bfloat16 l1 = __float2bfloat16(y - __bfloat162float(h1));
    __nv_bfloat162 hh; hh.x = h0; hh.y = h1;
    __nv_bfloat162 ll; ll.x = l0; ll.y = l1;
    h = *(uint32_t*)&hh;
    l = *(uint32_t*)&ll;
}
__device__ __forceinline__ float2 unsplit(uint32_t h, uint32_t l) {
    __nv_bfloat162 hh = *(__nv_bfloat162*)&h;
    __nv_bfloat162 ll = *(__nv_bfloat162*)&l;
    return make_float2(__bfloat162float(hh.x) + __bfloat162float(ll.x),
                       __bfloat162float(hh.y) + __bfloat162float(ll.y));
}

// ---------------------------------------------------------------------------
// fp32 -> bf16 (hi, lo) split kernel
// ---------------------------------------------------------------------------
__global__ __launch_bounds__(256)
void split_bf16_kernel(const float* __restrict__ src,
                       __nv_bfloat16* __restrict__ hi,
                       __nv_bfloat16* __restrict__ lo, int n4)
{
    int i = blockIdx.x * 256 + threadIdx.x;
    if (i >= n4) return;
    float4 v = ((const float4*)src)[i];
    uint32_t h0, l0, h1, l1;
    split2(v.x, v.y, h0, l0);
    split2(v.z, v.w, h1, l1);
    ((uint32_t*)hi)[2 * i]     = h0;
    ((uint32_t*)hi)[2 * i + 1] = h1;
    ((uint32_t*)lo)[2 * i]     = l0;
    ((uint32_t*)lo)[2 * i + 1] = l1;
}

// ---------------------------------------------------------------------------
// Tensor-core GEMM (3-term bf16 split). EPI=0: fp32 C (+bias). EPI=1: QKV
// epilogue — bias, head-major remap, q-scaling, bf16 hi/lo split stores.
// (Byte-identical to the 967us run.)
// ---------------------------------------------------------------------------
#define GM_SMEM_BYTES 81920

template<int EPI>
__global__ __launch_bounds__(256, 2)
void gemm_mma_kernel(const __nv_bfloat16* __restrict__ Ah, const __nv_bfloat16* __restrict__ Al,
                     const __nv_bfloat16* __restrict__ Bh, const __nv_bfloat16* __restrict__ Bl,
                     const float* __restrict__ bias, float* __restrict__ C,
                     int M, int N, int K)
{
    __nv_bfloat16* sb = (__nv_bfloat16*)dynsm;
    const uint32_t sb32 = (uint32_t)__cvta_generic_to_shared(sb);

    const int tid  = threadIdx.x;
    const int warp = tid >> 5, lane = tid & 31;
    const int wm = warp >> 2, wn = warp & 3;
    const int gr = lane >> 2, c4 = lane & 3;
    const int m0 = blockIdx.y * 128, n0 = blockIdx.x * 128;

    const int l_row0 = tid >> 2,            l_cb0 = (tid & 3) << 3;
    const int l_row1 = (tid + 256) >> 2,    l_cb1 = ((tid + 256) & 3) << 3;

    float acc[4][4][4];
#pragma unroll
    for (int i = 0; i < 4; i++)
#pragma unroll
        for (int j = 0; j < 4; j++)
#pragma unroll
            for (int r = 0; r < 4; r++) acc[i][j][r] = 0.f;

    const int nkt = K >> 5;

    auto load_tile = [&](int stage, int kt) {
        const int k0 = kt << 5;
        const uint32_t st = sb32 + stage * 40960u;
        cp16(st + (uint32_t)(l_row0 * 80 + l_cb0 * 2),
             Ah + (size_t)(m0 + l_row0) * K + k0 + l_cb0);
        cp16(st + (uint32_t)(l_row1 * 80 + l_cb1 * 2),
             Ah + (size_t)(m0 + l_row1) * K + k0 + l_cb1);
        cp16(st + 10240u + (uint32_t)(l_row0 * 80 + l_cb0 * 2),
             Al + (size_t)(m0 + l_row0) * K + k0 + l_cb0);
        cp16(st + 10240u + (uint32_t)(l_row1 * 80 + l_cb1 * 2),
             Al + (size_t)(m0 + l_row1) * K + k0 + l_cb1);
        cp16(st + 20480u + (uint32_t)(l_row0 * 80 + l_cb0 * 2),
             Bh + (size_t)(n0 + l_row0) * K + k0 + l_cb0);
        cp16(st + 20480u + (uint32_t)(l_row1 * 80 + l_cb1 * 2),
             Bh + (size_t)(n0 + l_row1) * K + k0 + l_cb1);
        cp16(st + 30720u + (uint32_t)(l_row0 * 80 + l_cb0 * 2),
             Bl + (size_t)(n0 + l_row0) * K + k0 + l_cb0);
        cp16(st + 30720u + (uint32_t)(l_row1 * 80 + l_cb1 * 2),
             Bl + (size_t)(n0 + l_row1) * K + k0 + l_cb1);
        asm volatile("cp.async.commit_group;");
    };

    load_tile(0, 0);
    load_tile(1, 1);

    for (int kt = 0; kt < nkt; kt++) {
        if (kt + 1 < nkt) asm volatile("cp.async.wait_group 1;");
        else              asm volatile("cp.async.wait_group 0;");
        __syncthreads();

        const __nv_bfloat16* sAh = sb + (kt & 1) * 20480;
        const __nv_bfloat16* sAl = sAh + 5120;
        const __nv_bfloat16* sBh = sAh + 10240;
        const __nv_bfloat16* sBl = sAh + 15360;

#pragma unroll
        for (int ks = 0; ks < 2; ks++) {
            const int kb = ks * 16 + 2 * c4;
            uint32_t bh[4][2], bl[4][2];
#pragma unroll
            for (int j = 0; j < 4; j++) {
                const int nrow = wn * 32 + j * 8 + gr;
                const __nv_bfloat16* p = sBh + nrow * 40 + kb;
                const __nv_bfloat16* q = sBl + nrow * 40 + kb;
                bh[j][0] = *(const uint32_t*)p;
                bh[j][1] = *(const uint32_t*)(p + 8);
                bl[j][0] = *(const uint32_t*)q;
                bl[j][1] = *(const uint32_t*)(q + 8);
            }
#pragma unroll
            for (int i = 0; i < 4; i++) {
                const int ar = wm * 64 + i * 16 + gr;
                const __nv_bfloat16* p = sAh + ar * 40 + kb;
                const __nv_bfloat16* q = sAl + ar * 40 + kb;
                uint32_t ah[4], al[4];
                ah[0] = *(const uint32_t*)p;
                ah[1] = *(const uint32_t*)(p + 320);
                ah[2] = *(const uint32_t*)(p + 8);
                ah[3] = *(const uint32_t*)(p + 328);
                al[0] = *(const uint32_t*)q;
                al[1] = *(const uint32_t*)(q + 320);
                al[2] = *(const uint32_t*)(q + 8);
                al[3] = *(const uint32_t*)(q + 328);
#pragma unroll
                for (int j = 0; j < 4; j++) {
                    mma_bf16(acc[i][j], ah, bh[j]);
                    mma_bf16(acc[i][j], ah, bl[j]);
                    mma_bf16(acc[i][j], al, bh[j]);
                }
            }
        }
        __syncthreads();
        if (kt + 2 < nkt) load_tile(kt & 1, kt + 2);
    }

#pragma unroll
    for (int j = 0; j < 4; j++) {
        const int gn = n0 + wn * 32 + j * 8 + 2 * c4;
        const float b0 = bias[gn], b1 = bias[gn + 1];
        if (EPI == 0) {
#pragma unroll
            for (int i = 0; i < 4; i++) {
                const int gm = m0 + wm * 64 + i * 16 + gr;
                float2 w0, w1;
                w0.x = acc[i][j][0] + b0; w0.y = acc[i][j][1] + b1;
                w1.x = acc[i][j][2] + b0; w1.y = acc[i][j][3] + b1;
                *(float2*)&C[(size_t)gm * N + gn] = w0;
                *(float2*)&C[(size_t)(gm + 8) * N + gn] = w1;
            }
        } else {
            const int part = gn / DIM;
            const int rem  = gn - part * DIM;
            const int hh   = rem / HDIM;
            const int dd   = rem - hh * HDIM;          // even
            uint32_t* dsth;
            uint32_t* dstl;
            float sc = 1.f;
            if (part == 0)      { dsth = (uint32_t*)g_qh; dstl = (uint32_t*)g_ql; sc = QSCALE; }
            else if (part == 1) { dsth = (uint32_t*)g_kh; dstl = (uint32_t*)g_kl; }
            else                { dsth = (uint32_t*)g_vh; dstl = (uint32_t*)g_vl; }
#pragma unroll
            for (int i = 0; i < 4; i++) {
                const int gm = m0 + wm * 64 + i * 16 + gr;
                const int b_ = gm >> 10, seq = gm & 1023;
                const size_t idx = (((size_t)(b_ * HEADS + hh) << 10) + seq) * 36 + (dd >> 1);
                uint32_t h_, l_;
                split2((acc[i][j][0] + b0) * sc, (acc[i][j][1] + b1) * sc, h_, l_);
                dsth[idx] = h_; dstl[idx] = l_;
                split2((acc[i][j][2] + b0) * sc, (acc[i][j][3] + b1) * sc, h_, l_);
                dsth[idx + 8 * 36] = h_; dstl[idx + 8 * 36] = l_;
            }
        }
    }
}

// ---------------------------------------------------------------------------
// Attention v6 (FA2-style): 128-query tile, 256 threads (8 warps), each warp
// owns 16 whole query rows. Scores, online softmax, and P all stay in
// registers — the m16n8 accumulator fragment IS the m16n8k16 A fragment.
// No P smem round-trip; ONE block barrier per KV tile.
//
// smem (bytes):
//   sQh @0, sQl @22528                 (each [128][88] bf16 = 22528)
//   KV  @45056: 2 bufs x {Kh,Kl,Vh,Vl} (each [64][88] bf16 = 11264; buf=45056)
// total 135168 bytes dynamic smem.
// ---------------------------------------------------------------------------
#define AT_SMEM_BYTES 135168

__global__ __launch_bounds__(256)
void attn_kernel(float* __restrict__ loss_out)
{
    __nv_bfloat16* smbf = (__nv_bfloat16*)dynsm;
    __nv_bfloat16* sQh = smbf;
    __nv_bfloat16* sQl = smbf + 11264;

    const uint32_t smu   = (uint32_t)__cvta_generic_to_shared(smbf);
    const uint32_t kvb32 = smu + 45056u;

    const int tid  = threadIdx.x;
    const int warp = tid >> 5, lane = tid & 31;
    const int gr = lane >> 2, c4 = lane & 3;

    const int bh = blockIdx.y, b = bh >> 4, h = bh & 15;
    const int n0 = blockIdx.x * 128;

    // ---- K/V tile prefetch (4 arrays x 64 rows x 9 chunks = 2304) ----
    auto prefetch = [&](int t, int buf) {
        const int kt = t & 15;
        const __nv_bfloat16* s0 = (t < 16) ? g_kh : g_ekh;
        const __nv_bfloat16* s1 = (t < 16) ? g_kl : g_ekl;
        const __nv_bfloat16* s2 = (t < 16) ? g_vh : g_evh;
        const __nv_bfloat16* s3 = (t < 16) ? g_vl : g_evl;
        const size_t toff = (((size_t)bh << 10) + kt * 64) * HDIM;
#pragma unroll
        for (int r = 0; r < 9; r++) {
            int e = tid + r * 256;
            int arr = e / 576, rem = e - arr * 576;
            int row = rem / 9,  ch  = rem - row * 9;
            const __nv_bfloat16* src =
                (arr == 0 ? s0 : arr == 1 ? s1 : arr == 2 ? s2 : s3)
                + toff + row * HDIM + ch * 8;
            cp16(kvb32 + buf * 45056u + arr * 11264u
                       + (uint32_t)(row * 176 + ch * 16), src);
        }
        asm volatile("cp.async.commit_group;");
    };
    prefetch(0, 0);

    // ---- zero pads (cols 72..87): Q arrays (128 rows) + 8 KV arrays ----
    for (int i = tid; i < 2048; i += 256) {
        int arr = i >> 10, rem = i & 1023;
        int row = rem >> 3, cp = rem & 7;
        *(uint32_t*)(smbf + arr * 11264 + row * 88 + 72 + 2 * cp) = 0;
    }
    for (int i = tid; i < 4096; i += 256) {
        int arr = i >> 9, rem = i & 511;
        int row = rem >> 3, cp = rem & 7;
        *(uint32_t*)(smbf + 22528 + arr * 5632 + row * 88 + 72 + 2 * cp) = 0;
    }

    // ---- load Q tile (bf16 hi/lo, pre-scaled): 128 rows x 36 chunks ----
    {
        const uint32_t* qh = (const uint32_t*)g_qh;
        const uint32_t* ql = (const uint32_t*)g_ql;
        const size_t qoff = (((size_t)bh << 10) + n0) * 36;
#pragma unroll
        for (int r = 0; r < 18; r++) {
            int e = tid + r * 256;                    // 0..4607
            int row = e / 36, ch = e - row * 36;
            size_t gi = qoff + row * 36 + ch;
            *(uint32_t*)(sQh + row * 88 + ch * 2) = qh[gi];
            *(uint32_t*)(sQl + row * 88 + ch * 2) = ql[gi];
        }
    }

    float lsum = 0.f;
    float m0 = -1e30f, m1 = -1e30f, l0 = 0.f, l1 = 0.f;
    float oacc[9][4];
#pragma unroll
    for (int j = 0; j < 9; j++)
#pragma unroll
        for (int r = 0; r < 4; r++) oacc[j][r] = 0.f;

    const int qrow = warp * 16 + gr;                  // this thread's row (and +8)

#pragma unroll 1
    for (int t = 0; t < 32; t++) {
        const int buf = t & 1;

        asm volatile("cp.async.wait_group 0;");
        __syncthreads();
        if (t + 1 < 32) prefetch(t + 1, buf ^ 1);

        const __nv_bfloat16* sKh = smbf + 22528 + buf * 22528;
        const __nv_bfloat16* sKl = sKh + 5632;
        const uint32_t vh_base = kvb32 + buf * 45056u + 22528u;

        // ---- scores: S[16x64] per warp, register-resident ----
        float sacc[8][4];
#pragma unroll
        for (int j = 0; j < 8; j++)
#pragma unroll
            for (int r = 0; r < 4; r++) sacc[j][r] = 0.f;

#pragma unroll
        for (int ks = 0; ks < 5; ks++) {
            const int kb = ks * 16 + 2 * c4;
            const __nv_bfloat16* p = sQh + qrow * 88 + kb;
            const __nv_bfloat16* q = sQl + qrow * 88 + kb;
            uint32_t ah[4], al[4];
            ah[0] = *(const uint32_t*)p;
            ah[1] = *(const uint32_t*)(p + 8 * 88);
            ah[2] = *(const uint32_t*)(p + 8);
            ah[3] = *(const uint32_t*)(p + 8 * 88 + 8);
            al[0] = *(const uint32_t*)q;
            al[1] = *(const uint32_t*)(q + 8 * 88);
            al[2] = *(const uint32_t*)(q + 8);
            al[3] = *(const uint32_t*)(q + 8 * 88 + 8);
#pragma unroll
            for (int j = 0; j < 8; j++) {
                const __nv_bfloat16* kp = sKh + (j * 8 + gr) * 88 + kb;
                const __nv_bfloat16* kq = sKl + (j * 8 + gr) * 88 + kb;
                uint32_t bh2[2], bl2[2];
                bh2[0] = *(const uint32_t*)kp;
                bh2[1] = *(const uint32_t*)(kp + 8);
                bl2[0] = *(const uint32_t*)kq;
                bl2[1] = *(const uint32_t*)(kq + 8);
                mma_bf16(sacc[j], ah, bh2);
                mma_bf16(sacc[j], ah, bl2);
                mma_bf16(sacc[j], al, bh2);
            }
        }

        // ---- online softmax, fully in registers (rows qrow, qrow+8) ----
        {
            float t0 = -1e30f, t1 = -1e30f;
#pragma unroll
            for (int j = 0; j < 8; j++) {
                t0 = fmaxf(t0, fmaxf(sacc[j][0], sacc[j][1]));
                t1 = fmaxf(t1, fmaxf(sacc[j][2], sacc[j][3]));
            }
            t0 = fmaxf(t0, __shfl_xor_sync(0xffffffffu, t0, 1));
            t0 = fmaxf(t0, __shfl_xor_sync(0xffffffffu, t0, 2));
            t1 = fmaxf(t1, __shfl_xor_sync(0xffffffffu, t1, 1));
            t1 = fmaxf(t1, __shfl_xor_sync(0xffffffffu, t1, 2));
            const float nm0 = fmaxf(m0, t0), nm1 = fmaxf(m1, t1);
            const float cr0 = __expf(m0 - nm0), cr1 = __expf(m1 - nm1);
            float s0 = 0.f, s1 = 0.f;
#pragma unroll
            for (int j = 0; j < 8; j++) {
                sacc[j][0] = __expf(sacc[j][0] - nm0);
                sacc[j][1] = __expf(sacc[j][1] - nm0);
                sacc[j][2] = __expf(sacc[j][2] - nm1);
                sacc[j][3] = __expf(sacc[j][3] - nm1);
                s0 += sacc[j][0] + sacc[j][1];
                s1 += sacc[j][2] + sacc[j][3];
            }
            s0 += __shfl_xor_sync(0xffffffffu, s0, 1);
            s0 += __shfl_xor_sync(0xffffffffu, s0, 2);
            s1 += __shfl_xor_sync(0xffffffffu, s1, 1);
            s1 += __shfl_xor_sync(0xffffffffu, s1, 2);
            l0 = l0 * cr0 + s0; l1 = l1 * cr1 + s1;
            m0 = nm0; m1 = nm1;
#pragma unroll
            for (int j = 0; j < 9; j++) {
                oacc[j][0] *= cr0; oacc[j][1] *= cr0;
                oacc[j][2] *= cr1; oacc[j][3] *= cr1;
            }
        }

        // ---- PV: P packs straight from sacc into A fragments ----
#pragma unroll
        for (int ks = 0; ks < 4; ks++) {
            uint32_t ph[4], pl[4];
            split2(sacc[2*ks][0],   sacc[2*ks][1],   ph[0], pl[0]);
            split2(sacc[2*ks][2],   sacc[2*ks][3],   ph[1], pl[1]);
            split2(sacc[2*ks+1][0], sacc[2*ks+1][1], ph[2], pl[2]);
            split2(sacc[2*ks+1][2], sacc[2*ks+1][3], ph[3], pl[3]);
            const uint32_t rowb = vh_base +
                (uint32_t)(((ks * 16 + (lane & 15)) * 88) * 2);
#pragma unroll
            for (int j = 0; j < 9; j++) {
                const uint32_t va = rowb + (uint32_t)((j * 8) * 2);
                uint32_t vh2[2], vl2[2];
                ldsm_x2_trans(vh2[0], vh2[1], va);
                ldsm_x2_trans(vl2[0], vl2[1], va + 11264u);
                mma_bf16(oacc[j], ph, vh2);
                mma_bf16(oacc[j], ph, vl2);
                mma_bf16(oacc[j], pl, vh2);
            }
        }

        // ---- pass epilogues (register/global only — no barriers) ----
        if (t == 15) {
            const float i0 = 1.0f / l0, i1 = 1.0f / l1;
            const int q0 = n0 + qrow;
            uint32_t* dh = (uint32_t*)g_oh;
            uint32_t* dl = (uint32_t*)g_ol;
#pragma unroll
            for (int j = 0; j < 9; j++) {
                const int dim = j * 8 + 2 * c4;
                const size_t i0x = (((size_t)(b * SEQ + q0)) * DIM
                                    + h * HDIM + dim) >> 1;
                const size_t i1x = (((size_t)(b * SEQ + q0 + 8)) * DIM
                                    + h * HDIM + dim) >> 1;
                uint32_t hh, ll;
                split2(oacc[j][0] * i0, oacc[j][1] * i0, hh, ll);
                dh[i0x] = hh; dl[i0x] = ll;
                split2(oacc[j][2] * i1, oacc[j][3] * i1, hh, ll);
                dh[i1x] = hh; dl[i1x] = ll;
            }
            m0 = -1e30f; m1 = -1e30f; l0 = 0.f; l1 = 0.f;
#pragma unroll
            for (int j = 0; j < 9; j++)
#pragma unroll
                for (int r = 0; r < 4; r++) oacc[j][r] = 0.f;
        } else if (t == 31) {
            const float i0 = 1.0f / l0, i1 = 1.0f / l1;
            const int q0 = n0 + qrow;
            const uint32_t* dh = (const uint32_t*)g_oh;
            const uint32_t* dl = (const uint32_t*)g_ol;
#pragma unroll
            for (int j = 0; j < 9; j++) {
                const int dim = j * 8 + 2 * c4;
                const size_t i0x = (((size_t)(b * SEQ + q0)) * DIM
                                    + h * HDIM + dim) >> 1;
                const size_t i1x = (((size_t)(b * SEQ + q0 + 8)) * DIM
                                    + h * HDIM + dim) >> 1;
                float2 x0 = unsplit(dh[i0x], dl[i0x]);
                float2 x1 = unsplit(dh[i1x], dl[i1x]);
                float e0 = x0.x - oacc[j][0] * i0;
                float e1 = x0.y - oacc[j][1] * i0;
                float e2 = x1.x - oacc[j][2] * i1;
                float e3 = x1.y - oacc[j][3] * i1;
                lsum += e0*e0 + e1*e1 + e2*e2 + e3*e3;
            }
        }
    }

    // loss reduction: warp reduce + one atomic per warp
    lsum *= (1.0f / TOTAL_ELEMS);
#pragma unroll
    for (int o = 16; o > 0; o >>= 1)
        lsum += __shfl_down_sync(0xffffffffu, lsum, o);
    if (lane == 0) atomicAdd(loss_out, lsum);
}

// ---------------------------------------------------------------------------
extern "C" void kernel_launch(void* const* d_in, const int* in_sizes, int n_in,
                              void* d_out, int out_size)
{
    const float* x      = (const float*)d_in[0];
    const float* enc_k  = (const float*)d_in[1];
    const float* enc_v  = (const float*)d_in[2];
    const float* qkv_w  = (const float*)d_in[3];
    const float* qkv_b  = (const float*)d_in[4];
    const float* proj_w = (const float*)d_in[5];
    const float* proj_b = (const float*)d_in[6];
    float* out = (float*)d_out;
    float* loss_ptr = out + (out_size - 1);

    __nv_bfloat16 *xh, *xl, *wqh, *wql, *wph, *wpl, *oh, *ol;
    __nv_bfloat16 *ekh, *ekl, *evh, *evl;
    cudaGetSymbolAddress((void**)&xh,  g_xh);   cudaGetSymbolAddress((void**)&xl,  g_xl);
    cudaGetSymbolAddress((void**)&wqh, g_wqh);  cudaGetSymbolAddress((void**)&wql, g_wql);
    cudaGetSymbolAddress((void**)&wph, g_wph);  cudaGetSymbolAddress((void**)&wpl, g_wpl);
    cudaGetSymbolAddress((void**)&oh,  g_oh);   cudaGetSymbolAddress((void**)&ol,  g_ol);
    cudaGetSymbolAddress((void**)&ekh, g_ekh);  cudaGetSymbolAddress((void**)&ekl, g_ekl);
    cudaGetSymbolAddress((void**)&evh, g_evh);  cudaGetSymbolAddress((void**)&evl, g_evl);

    static bool attr_set = false;
    if (!attr_set) {
        cudaFuncSetAttribute(attn_kernel,
                             cudaFuncAttributeMaxDynamicSharedMemorySize, AT_SMEM_BYTES);
        cudaFuncSetAttribute(gemm_mma_kernel<0>,
                             cudaFuncAttributeMaxDynamicSharedMemorySize, GM_SMEM_BYTES);
        cudaFuncSetAttribute(gemm_mma_kernel<1>,
                             cudaFuncAttributeMaxDynamicSharedMemorySize, GM_SMEM_BYTES);
        attr_set = true;
    }

    cudaMemsetAsync(loss_ptr, 0, sizeof(float));

    // 0) fp32 -> bf16 hi/lo splits (GEMM inputs + encoder K/V)
    {
        int n4x = (ROWS * DIM) / 4;
        int n4q = (QKVN * DIM) / 4;
        int n4p = (DIM * DIM) / 4;
        split_bf16_kernel<<<(n4x + 255) / 256, 256>>>(x,      xh,  xl,  n4x);
        split_bf16_kernel<<<(n4q + 255) / 256, 256>>>(qkv_w,  wqh, wql, n4q);
        split_bf16_kernel<<<(n4p + 255) / 256, 256>>>(proj_w, wph, wpl, n4p);
        split_bf16_kernel<<<(n4x + 255) / 256, 256>>>(enc_k,  ekh, ekl, n4x);
        split_bf16_kernel<<<(n4x + 255) / 256, 256>>>(enc_v,  evh, evl, n4x);
    }

    // 1) QKV GEMM (tensor cores) -> head-major bf16 hi/lo Q(scaled)/K/V
    gemm_mma_kernel<1><<<dim3(QKVN / 128, ROWS / 128), 256, GM_SMEM_BYTES>>>(
        xh, xl, wqh, wql, qkv_b, nullptr, ROWS, QKVN, DIM);

    // 2) Dual attention + loss (tensor cores, FA2 register P) -> g_oh/g_ol
    attn_kernel<<<dim3(SEQ / 128, BATCH * HEADS), 256, AT_SMEM_BYTES>>>(loss_ptr);

    // 3) proj GEMM (tensor cores) -> out
    gemm_mma_kernel<0><<<dim3(DIM / 128, ROWS / 128), 256, GM_SMEM_BYTES>>>(
        oh, ol, wph, wpl, proj_b, out, ROWS, DIM, DIM);
}

// round 13
// speedup vs baseline: 1.1995x; 1.0187x over previous
#include <cuda_runtime.h>
#include <cuda_bf16.h>
#include <cstdint>
#include <cstddef>

// Problem constants (fixed by setup_inputs)
#define BATCH 4
#define SEQ   1024
#define DIM   1152
#define HEADS 16
#define HDIM  72
#define ROWS  (BATCH*SEQ)          // 4096
#define QKVN  (3*DIM)              // 3456
#define TOTAL_ELEMS 4718592.0f     // B*H*N*hd for loss mean
#define QSCALE 0.11785113f         // 72^-0.5

// Scratch (static device allocation — allowed). All bf16 hi/lo pairs.
__device__ __align__(16) __nv_bfloat16 g_xh [(size_t)ROWS * DIM];
__device__ __align__(16) __nv_bfloat16 g_xl [(size_t)ROWS * DIM];
__device__ __align__(16) __nv_bfloat16 g_wqh[(size_t)QKVN * DIM];
__device__ __align__(16) __nv_bfloat16 g_wql[(size_t)QKVN * DIM];
__device__ __align__(16) __nv_bfloat16 g_wph[(size_t)DIM * DIM];
__device__ __align__(16) __nv_bfloat16 g_wpl[(size_t)DIM * DIM];
// head-major [bh][seq][72] bf16 Q/K/V (hi/lo), written by QKV GEMM epilogue
__device__ __align__(16) __nv_bfloat16 g_qh [(size_t)ROWS * DIM];
__device__ __align__(16) __nv_bfloat16 g_ql [(size_t)ROWS * DIM];
__device__ __align__(16) __nv_bfloat16 g_kh [(size_t)ROWS * DIM];
__device__ __align__(16) __nv_bfloat16 g_kl [(size_t)ROWS * DIM];
__device__ __align__(16) __nv_bfloat16 g_vh [(size_t)ROWS * DIM];
__device__ __align__(16) __nv_bfloat16 g_vl [(size_t)ROWS * DIM];
// encoder K/V pre-split (same [bh][seq][72] layout as the fp32 inputs)
__device__ __align__(16) __nv_bfloat16 g_ekh[(size_t)ROWS * DIM];
__device__ __align__(16) __nv_bfloat16 g_ekl[(size_t)ROWS * DIM];
__device__ __align__(16) __nv_bfloat16 g_evh[(size_t)ROWS * DIM];
__device__ __align__(16) __nv_bfloat16 g_evl[(size_t)ROWS * DIM];
// attention output (hi/lo) -> proj GEMM input
__device__ __align__(16) __nv_bfloat16 g_oh [(size_t)ROWS * DIM];
__device__ __align__(16) __nv_bfloat16 g_ol [(size_t)ROWS * DIM];

extern __shared__ char dynsm[];

// ---------------------------------------------------------------------------
// helpers
// ---------------------------------------------------------------------------
__device__ __forceinline__ void cp16(uint32_t dst, const void* src) {
    asm volatile("cp.async.cg.shared.global [%0], [%1], 16;" :: "r"(dst), "l"(src));
}
__device__ __forceinline__ void mma_bf16(float* d, const uint32_t* a, const uint32_t* b) {
    asm volatile(
        "mma.sync.aligned.m16n8k16.row.col.f32.bf16.bf16.f32 "
        "{%0,%1,%2,%3}, {%4,%5,%6,%7}, {%8,%9}, {%0,%1,%2,%3};"
        : "+f"(d[0]), "+f"(d[1]), "+f"(d[2]), "+f"(d[3])
        : "r"(a[0]), "r"(a[1]), "r"(a[2]), "r"(a[3]), "r"(b[0]), "r"(b[1]));
}
__device__ __forceinline__ void ldsm_x2_trans(uint32_t& r0, uint32_t& r1, uint32_t saddr) {
    asm volatile("ldmatrix.sync.aligned.m8n8.x2.trans.shared.b16 {%0,%1}, [%2];"
                 : "=r"(r0), "=r"(r1) : "r"(saddr));
}
__device__ __forceinline__ void ldsm_x4_trans(uint32_t& r0, uint32_t& r1,
                                              uint32_t& r2, uint32_t& r3, uint32_t saddr) {
    asm volatile("ldmatrix.sync.aligned.m8n8.x4.trans.shared.b16 {%0,%1,%2,%3}, [%4];"
                 : "=r"(r0), "=r"(r1), "=r"(r2), "=r"(r3) : "r"(saddr));
}
__device__ __forceinline__ void split2(float x, float y, uint32_t& h, uint32_t& l) {
    __nv_bfloat16 h0 = __float2bfloat16(x);
    __nv_bfloat16 h1 = __float2bfloat16(y);
    __nv_bfloat16 l0 = __float2bfloat16(x - __bfloat162float(h0));
    __nv_bfloat16 l1 = __float2bfloat16(y - __bfloat162float(h1));
    __nv_bfloat162 hh; hh.x = h0; hh.y = h1;
    __nv_bfloat162 ll; ll.x = l0; ll.y = l1;
    h = *(uint32_t*)&hh;
    l = *(uint32_t*)&ll;
}
__device__ __forceinline__ float2 unsplit(uint32_t h, uint32_t l) {
    __nv_bfloat162 hh = *(__nv_bfloat162*)&h;
    __nv_bfloat162 ll = *(__nv_bfloat162*)&l;
    return make_float2(__bfloat162float(hh.x) + __bfloat162float(ll.x),
                       __bfloat162float(hh.y) + __bfloat162float(ll.y));
}

// ---------------------------------------------------------------------------
// Fused fp32 -> bf16 (hi, lo) split over all 5 input tensors (one launch).
// Region sizes in float4 units.
// ---------------------------------------------------------------------------
#define N4_X  ((ROWS * DIM) / 4)      // 1179648
#define N4_WQ ((QKVN * DIM) / 4)      //  995328
#define N4_WP ((DIM * DIM) / 4)       //  331776
#define N4_ALL (N4_X + N4_WQ + N4_WP + N4_X + N4_X)   // 4866048

__global__ __launch_bounds__(256)
void split_all_kernel(const float* __restrict__ x,    const float* __restrict__ wq,
                      const float* __restrict__ wp,   const float* __restrict__ ek,
                      const float* __restrict__ ev)
{
    int i = blockIdx.x * 256 + threadIdx.x;
    if (i >= N4_ALL) return;
    const float* src;
    __nv_bfloat16 *hi, *lo;
    int o = i;
    if (o < N4_X)                   { src = x;  hi = g_xh;  lo = g_xl;  }
    else if ((o -= N4_X) < N4_WQ)   { src = wq; hi = g_wqh; lo = g_wql; }
    else if ((o -= N4_WQ) < N4_WP)  { src = wp; hi = g_wph; lo = g_wpl; }
    else if ((o -= N4_WP) < N4_X)   { src = ek; hi = g_ekh; lo = g_ekl; }
    else                            { o -= N4_X; src = ev; hi = g_evh; lo = g_evl; }

    float4 v = ((const float4*)src)[o];
    uint32_t h0, l0, h1, l1;
    split2(v.x, v.y, h0, l0);
    split2(v.z, v.w, h1, l1);
    ((uint32_t*)hi)[2 * o]     = h0;
    ((uint32_t*)hi)[2 * o + 1] = h1;
    ((uint32_t*)lo)[2 * o]     = l0;
    ((uint32_t*)lo)[2 * o + 1] = l1;
}

// ---------------------------------------------------------------------------
// Tensor-core GEMM (3-term bf16 split). EPI=0: fp32 C (+bias). EPI=1: QKV
// epilogue — bias, head-major remap, q-scaling, bf16 hi/lo split stores.
// (Byte-identical to the 837us run.)
// ---------------------------------------------------------------------------
#define GM_SMEM_BYTES 81920

template<int EPI>
__global__ __launch_bounds__(256, 2)
void gemm_mma_kernel(const __nv_bfloat16* __restrict__ Ah, const __nv_bfloat16* __restrict__ Al,
                     const __nv_bfloat16* __restrict__ Bh, const __nv_bfloat16* __restrict__ Bl,
                     const float* __restrict__ bias, float* __restrict__ C,
                     int M, int N, int K)
{
    __nv_bfloat16* sb = (__nv_bfloat16*)dynsm;
    const uint32_t sb32 = (uint32_t)__cvta_generic_to_shared(sb);

    const int tid  = threadIdx.x;
    const int warp = tid >> 5, lane = tid & 31;
    const int wm = warp >> 2, wn = warp & 3;
    const int gr = lane >> 2, c4 = lane & 3;
    const int m0 = blockIdx.y * 128, n0 = blockIdx.x * 128;

    const int l_row0 = tid >> 2,            l_cb0 = (tid & 3) << 3;
    const int l_row1 = (tid + 256) >> 2,    l_cb1 = ((tid + 256) & 3) << 3;

    float acc[4][4][4];
#pragma unroll
    for (int i = 0; i < 4; i++)
#pragma unroll
        for (int j = 0; j < 4; j++)
#pragma unroll
            for (int r = 0; r < 4; r++) acc[i][j][r] = 0.f;

    const int nkt = K >> 5;

    auto load_tile = [&](int stage, int kt) {
        const int k0 = kt << 5;
        const uint32_t st = sb32 + stage * 40960u;
        cp16(st + (uint32_t)(l_row0 * 80 + l_cb0 * 2),
             Ah + (size_t)(m0 + l_row0) * K + k0 + l_cb0);
        cp16(st + (uint32_t)(l_row1 * 80 + l_cb1 * 2),
             Ah + (size_t)(m0 + l_row1) * K + k0 + l_cb1);
        cp16(st + 10240u + (uint32_t)(l_row0 * 80 + l_cb0 * 2),
             Al + (size_t)(m0 + l_row0) * K + k0 + l_cb0);
        cp16(st + 10240u + (uint32_t)(l_row1 * 80 + l_cb1 * 2),
             Al + (size_t)(m0 + l_row1) * K + k0 + l_cb1);
        cp16(st + 20480u + (uint32_t)(l_row0 * 80 + l_cb0 * 2),
             Bh + (size_t)(n0 + l_row0) * K + k0 + l_cb0);
        cp16(st + 20480u + (uint32_t)(l_row1 * 80 + l_cb1 * 2),
             Bh + (size_t)(n0 + l_row1) * K + k0 + l_cb1);
        cp16(st + 30720u + (uint32_t)(l_row0 * 80 + l_cb0 * 2),
             Bl + (size_t)(n0 + l_row0) * K + k0 + l_cb0);
        cp16(st + 30720u + (uint32_t)(l_row1 * 80 + l_cb1 * 2),
             Bl + (size_t)(n0 + l_row1) * K + k0 + l_cb1);
        asm volatile("cp.async.commit_group;");
    };

    load_tile(0, 0);
    load_tile(1, 1);

    for (int kt = 0; kt < nkt; kt++) {
        if (kt + 1 < nkt) asm volatile("cp.async.wait_group 1;");
        else              asm volatile("cp.async.wait_group 0;");
        __syncthreads();

        const __nv_bfloat16* sAh = sb + (kt & 1) * 20480;
        const __nv_bfloat16* sAl = sAh + 5120;
        const __nv_bfloat16* sBh = sAh + 10240;
        const __nv_bfloat16* sBl = sAh + 15360;

#pragma unroll
        for (int ks = 0; ks < 2; ks++) {
            const int kb = ks * 16 + 2 * c4;
            uint32_t bh[4][2], bl[4][2];
#pragma unroll
            for (int j = 0; j < 4; j++) {
                const int nrow = wn * 32 + j * 8 + gr;
                const __nv_bfloat16* p = sBh + nrow * 40 + kb;
                const __nv_bfloat16* q = sBl + nrow * 40 + kb;
                bh[j][0] = *(const uint32_t*)p;
                bh[j][1] = *(const uint32_t*)(p + 8);
                bl[j][0] = *(const uint32_t*)q;
                bl[j][1] = *(const uint32_t*)(q + 8);
            }
#pragma unroll
            for (int i = 0; i < 4; i++) {
                const int ar = wm * 64 + i * 16 + gr;
                const __nv_bfloat16* p = sAh + ar * 40 + kb;
                const __nv_bfloat16* q = sAl + ar * 40 + kb;
                uint32_t ah[4], al[4];
                ah[0] = *(const uint32_t*)p;
                ah[1] = *(const uint32_t*)(p + 320);
                ah[2] = *(const uint32_t*)(p + 8);
                ah[3] = *(const uint32_t*)(p + 328);
                al[0] = *(const uint32_t*)q;
                al[1] = *(const uint32_t*)(q + 320);
                al[2] = *(const uint32_t*)(q + 8);
                al[3] = *(const uint32_t*)(q + 328);
#pragma unroll
                for (int j = 0; j < 4; j++) {
                    mma_bf16(acc[i][j], ah, bh[j]);
                    mma_bf16(acc[i][j], ah, bl[j]);
                    mma_bf16(acc[i][j], al, bh[j]);
                }
            }
        }
        __syncthreads();
        if (kt + 2 < nkt) load_tile(kt & 1, kt + 2);
    }

#pragma unroll
    for (int j = 0; j < 4; j++) {
        const int gn = n0 + wn * 32 + j * 8 + 2 * c4;
        const float b0 = bias[gn], b1 = bias[gn + 1];
        if (EPI == 0) {
#pragma unroll
            for (int i = 0; i < 4; i++) {
                const int gm = m0 + wm * 64 + i * 16 + gr;
                float2 w0, w1;
                w0.x = acc[i][j][0] + b0; w0.y = acc[i][j][1] + b1;
                w1.x = acc[i][j][2] + b0; w1.y = acc[i][j][3] + b1;
                *(float2*)&C[(size_t)gm * N + gn] = w0;
                *(float2*)&C[(size_t)(gm + 8) * N + gn] = w1;
            }
        } else {
            const int part = gn / DIM;
            const int rem  = gn - part * DIM;
            const int hh   = rem / HDIM;
            const int dd   = rem - hh * HDIM;          // even
            uint32_t* dsth;
            uint32_t* dstl;
            float sc = 1.f;
            if (part == 0)      { dsth = (uint32_t*)g_qh; dstl = (uint32_t*)g_ql; sc = QSCALE; }
            else if (part == 1) { dsth = (uint32_t*)g_kh; dstl = (uint32_t*)g_kl; }
            else                { dsth = (uint32_t*)g_vh; dstl = (uint32_t*)g_vl; }
#pragma unroll
            for (int i = 0; i < 4; i++) {
                const int gm = m0 + wm * 64 + i * 16 + gr;
                const int b_ = gm >> 10, seq = gm & 1023;
                const size_t idx = (((size_t)(b_ * HEADS + hh) << 10) + seq) * 36 + (dd >> 1);
                uint32_t h_, l_;
                split2((acc[i][j][0] + b0) * sc, (acc[i][j][1] + b1) * sc, h_, l_);
                dsth[idx] = h_; dstl[idx] = l_;
                split2((acc[i][j][2] + b0) * sc, (acc[i][j][3] + b1) * sc, h_, l_);
                dsth[idx + 8 * 36] = h_; dstl[idx + 8 * 36] = l_;
            }
        }
    }
}

// ---------------------------------------------------------------------------
// Attention v7 (FA2 register P + ldmatrix.x4 V loads).
// 128-query tile, 256 threads (8 warps), warp owns 16 query rows.
// smem: sQh @0, sQl @22528 (each [128][88]); KV @45056: 2 bufs x {Kh,Kl,Vh,Vl}
// ([64][88] each, 11264 B). Total 135168 B.
// ---------------------------------------------------------------------------
#define AT_SMEM_BYTES 135168

__global__ __launch_bounds__(256)
void attn_kernel(float* __restrict__ loss_out)
{
    __nv_bfloat16* smbf = (__nv_bfloat16*)dynsm;
    __nv_bfloat16* sQh = smbf;
    __nv_bfloat16* sQl = smbf + 11264;

    const uint32_t smu   = (uint32_t)__cvta_generic_to_shared(smbf);
    const uint32_t kvb32 = smu + 45056u;

    const int tid  = threadIdx.x;
    const int warp = tid >> 5, lane = tid & 31;
    const int gr = lane >> 2, c4 = lane & 3;

    const int bh = blockIdx.y, b = bh >> 4, h = bh & 15;
    const int n0 = blockIdx.x * 128;

    auto prefetch = [&](int t, int buf) {
        const int kt = t & 15;
        const __nv_bfloat16* s0 = (t < 16) ? g_kh : g_ekh;
        const __nv_bfloat16* s1 = (t < 16) ? g_kl : g_ekl;
        const __nv_bfloat16* s2 = (t < 16) ? g_vh : g_evh;
        const __nv_bfloat16* s3 = (t < 16) ? g_vl : g_evl;
        const size_t toff = (((size_t)bh << 10) + kt * 64) * HDIM;
#pragma unroll
        for (int r = 0; r < 9; r++) {
            int e = tid + r * 256;
            int arr = e / 576, rem = e - arr * 576;
            int row = rem / 9,  ch  = rem - row * 9;
            const __nv_bfloat16* src =
                (arr == 0 ? s0 : arr == 1 ? s1 : arr == 2 ? s2 : s3)
                + toff + row * HDIM + ch * 8;
            cp16(kvb32 + buf * 45056u + arr * 11264u
                       + (uint32_t)(row * 176 + ch * 16), src);
        }
        asm volatile("cp.async.commit_group;");
    };
    prefetch(0, 0);

    // zero pads (cols 72..87)
    for (int i = tid; i < 2048; i += 256) {
        int arr = i >> 10, rem = i & 1023;
        int row = rem >> 3, cp = rem & 7;
        *(uint32_t*)(smbf + arr * 11264 + row * 88 + 72 + 2 * cp) = 0;
    }
    for (int i = tid; i < 4096; i += 256) {
        int arr = i >> 9, rem = i & 511;
        int row = rem >> 3, cp = rem & 7;
        *(uint32_t*)(smbf + 22528 + arr * 5632 + row * 88 + 72 + 2 * cp) = 0;
    }

    // load Q tile
    {
        const uint32_t* qh = (const uint32_t*)g_qh;
        const uint32_t* ql = (const uint32_t*)g_ql;
        const size_t qoff = (((size_t)bh << 10) + n0) * 36;
#pragma unroll
        for (int r = 0; r < 18; r++) {
            int e = tid + r * 256;
            int row = e / 36, ch = e - row * 36;
            size_t gi = qoff + row * 36 + ch;
            *(uint32_t*)(sQh + row * 88 + ch * 2) = qh[gi];
            *(uint32_t*)(sQl + row * 88 + ch * 2) = ql[gi];
        }
    }

    float lsum = 0.f;
    float m0 = -1e30f, m1 = -1e30f, l0 = 0.f, l1 = 0.f;
    float oacc[9][4];
#pragma unroll
    for (int j = 0; j < 9; j++)
#pragma unroll
        for (int r = 0; r < 4; r++) oacc[j][r] = 0.f;

    const int qrow = warp * 16 + gr;

#pragma unroll 1
    for (int t = 0; t < 32; t++) {
        const int buf = t & 1;

        asm volatile("cp.async.wait_group 0;");
        __syncthreads();
        if (t + 1 < 32) prefetch(t + 1, buf ^ 1);

        const __nv_bfloat16* sKh = smbf + 22528 + buf * 22528;
        const __nv_bfloat16* sKl = sKh + 5632;
        const uint32_t vh_base = kvb32 + buf * 45056u + 22528u;

        // ---- scores ----
        float sacc[8][4];
#pragma unroll
        for (int j = 0; j < 8; j++)
#pragma unroll
            for (int r = 0; r < 4; r++) sacc[j][r] = 0.f;

#pragma unroll
        for (int ks = 0; ks < 5; ks++) {
            const int kb = ks * 16 + 2 * c4;
            const __nv_bfloat16* p = sQh + qrow * 88 + kb;
            const __nv_bfloat16* q = sQl + qrow * 88 + kb;
            uint32_t ah[4], al[4];
            ah[0] = *(const uint32_t*)p;
            ah[1] = *(const uint32_t*)(p + 8 * 88);
            ah[2] = *(const uint32_t*)(p + 8);
            ah[3] = *(const uint32_t*)(p + 8 * 88 + 8);
            al[0] = *(const uint32_t*)q;
            al[1] = *(const uint32_t*)(q + 8 * 88);
            al[2] = *(const uint32_t*)(q + 8);
            al[3] = *(const uint32_t*)(q + 8 * 88 + 8);
#pragma unroll
            for (int j = 0; j < 8; j++) {
                const __nv_bfloat16* kp = sKh + (j * 8 + gr) * 88 + kb;
                const __nv_bfloat16* kq = sKl + (j * 8 + gr) * 88 + kb;
                uint32_t bh2[2], bl2[2];
                bh2[0] = *(const uint32_t*)kp;
                bh2[1] = *(const uint32_t*)(kp + 8);
                bl2[0] = *(const uint32_t*)kq;
                bl2[1] = *(const uint32_t*)(kq + 8);
                mma_bf16(sacc[j], ah, bh2);
                mma_bf16(sacc[j], ah, bl2);
                mma_bf16(sacc[j], al, bh2);
            }
        }

        // ---- online softmax in registers ----
        {
            float t0 = -1e30f, t1 = -1e30f;
#pragma unroll
            for (int j = 0; j < 8; j++) {
                t0 = fmaxf(t0, fmaxf(sacc[j][0], sacc[j][1]));
                t1 = fmaxf(t1, fmaxf(sacc[j][2], sacc[j][3]));
            }
            t0 = fmaxf(t0, __shfl_xor_sync(0xffffffffu, t0, 1));
            t0 = fmaxf(t0, __shfl_xor_sync(0xffffffffu, t0, 2));
            t1 = fmaxf(t1, __shfl_xor_sync(0xffffffffu, t1, 1));
            t1 = fmaxf(t1, __shfl_xor_sync(0xffffffffu, t1, 2));
            const float nm0 = fmaxf(m0, t0), nm1 = fmaxf(m1, t1);
            const float cr0 = __expf(m0 - nm0), cr1 = __expf(m1 - nm1);
            float s0 = 0.f, s1 = 0.f;
#pragma unroll
            for (int j = 0; j < 8; j++) {
                sacc[j][0] = __expf(sacc[j][0] - nm0);
                sacc[j][1] = __expf(sacc[j][1] - nm0);
                sacc[j][2] = __expf(sacc[j][2] - nm1);
                sacc[j][3] = __expf(sacc[j][3] - nm1);
                s0 += sacc[j][0] + sacc[j][1];
                s1 += sacc[j][2] + sacc[j][3];
            }
            s0 += __shfl_xor_sync(0xffffffffu, s0, 1);
            s0 += __shfl_xor_sync(0xffffffffu, s0, 2);
            s1 += __shfl_xor_sync(0xffffffffu, s1, 1);
            s1 += __shfl_xor_sync(0xffffffffu, s1, 2);
            l0 = l0 * cr0 + s0; l1 = l1 * cr1 + s1;
            m0 = nm0; m1 = nm1;
#pragma unroll
            for (int j = 0; j < 9; j++) {
                oacc[j][0] *= cr0; oacc[j][1] *= cr0;
                oacc[j][2] *= cr1; oacc[j][3] *= cr1;
            }
        }

        // ---- PV: register P fragments; V via ldmatrix.x4 (two j per load) ----
#pragma unroll
        for (int ks = 0; ks < 4; ks++) {
            uint32_t ph[4], pl[4];
            split2(sacc[2*ks][0],   sacc[2*ks][1],   ph[0], pl[0]);
            split2(sacc[2*ks][2],   sacc[2*ks][3],   ph[1], pl[1]);
            split2(sacc[2*ks+1][0], sacc[2*ks+1][1], ph[2], pl[2]);
            split2(sacc[2*ks+1][2], sacc[2*ks+1][3], ph[3], pl[3]);
            // x4 base: lanes 0-15 -> rows (ks*16 + lane), col block j;
            //          lanes 16-31 -> same rows, col block j+1
            const uint32_t va_base = vh_base +
                (uint32_t)(((ks * 16 + (lane & 15)) * 88) * 2) +
                (uint32_t)((lane >> 4) * 16);
#pragma unroll
            for (int jp = 0; jp < 8; jp += 2) {
                const uint32_t va = va_base + (uint32_t)(jp * 16);
                uint32_t vh4[4], vl4[4];
                ldsm_x4_trans(vh4[0], vh4[1], vh4[2], vh4[3], va);
                ldsm_x4_trans(vl4[0], vl4[1], vl4[2], vl4[3], va + 11264u);
                mma_bf16(oacc[jp],     ph, vh4);
                mma_bf16(oacc[jp],     ph, vl4);
                mma_bf16(oacc[jp],     pl, vh4);
                mma_bf16(oacc[jp + 1], ph, vh4 + 2);
                mma_bf16(oacc[jp + 1], ph, vl4 + 2);
                mma_bf16(oacc[jp + 1], pl, vh4 + 2);
            }
            {   // j = 8 remainder (x2: lanes 0-15 supply rows)
                const uint32_t va = vh_base +
                    (uint32_t)(((ks * 16 + (lane & 15)) * 88) * 2) +
                    (uint32_t)(8 * 16);
                uint32_t vh2[2], vl2[2];
                ldsm_x2_trans(vh2[0], vh2[1], va);
                ldsm_x2_trans(vl2[0], vl2[1], va + 11264u);
                mma_bf16(oacc[8], ph, vh2);
                mma_bf16(oacc[8], ph, vl2);
                mma_bf16(oacc[8], pl, vh2);
            }
        }

        // ---- pass epilogues ----
        if (t == 15) {
            const float i0 = 1.0f / l0, i1 = 1.0f / l1;
            const int q0 = n0 + qrow;
            uint32_t* dh = (uint32_t*)g_oh;
            uint32_t* dl = (uint32_t*)g_ol;
#pragma unroll
            for (int j = 0; j < 9; j++) {
                const int dim = j * 8 + 2 * c4;
                const size_t i0x = (((size_t)(b * SEQ + q0)) * DIM
                                    + h * HDIM + dim) >> 1;
                const size_t i1x = (((size_t)(b * SEQ + q0 + 8)) * DIM
                                    + h * HDIM + dim) >> 1;
                uint32_t hh, ll;
                split2(oacc[j][0] * i0, oacc[j][1] * i0, hh, ll);
                dh[i0x] = hh; dl[i0x] = ll;
                split2(oacc[j][2] * i1, oacc[j][3] * i1, hh, ll);
                dh[i1x] = hh; dl[i1x] = ll;
            }
            m0 = -1e30f; m1 = -1e30f; l0 = 0.f; l1 = 0.f;
#pragma unroll
            for (int j = 0; j < 9; j++)
#pragma unroll
                for (int r = 0; r < 4; r++) oacc[j][r] = 0.f;
        } else if (t == 31) {
            const float i0 = 1.0f / l0, i1 = 1.0f / l1;
            const int q0 = n0 + qrow;
            const uint32_t* dh = (const uint32_t*)g_oh;
            const uint32_t* dl = (const uint32_t*)g_ol;
#pragma unroll
            for (int j = 0; j < 9; j++) {
                const int dim = j * 8 + 2 * c4;
                const size_t i0x = (((size_t)(b * SEQ + q0)) * DIM
                                    + h * HDIM + dim) >> 1;
                const size_t i1x = (((size_t)(b * SEQ + q0 + 8)) * DIM
                                    + h * HDIM + dim) >> 1;
                float2 x0 = unsplit(dh[i0x], dl[i0x]);
                float2 x1 = unsplit(dh[i1x], dl[i1x]);
                float e0 = x0.x - oacc[j][0] * i0;
                float e1 = x0.y - oacc[j][1] * i0;
                float e2 = x1.x - oacc[j][2] * i1;
                float e3 = x1.y - oacc[j][3] * i1;
                lsum += e0*e0 + e1*e1 + e2*e2 + e3*e3;
            }
        }
    }

    lsum *= (1.0f / TOTAL_ELEMS);
#pragma unroll
    for (int o = 16; o > 0; o >>= 1)
        lsum += __shfl_down_sync(0xffffffffu, lsum, o);
    if (lane == 0) atomicAdd(loss_out, lsum);
}

// ---------------------------------------------------------------------------
extern "C" void kernel_launch(void* const* d_in, const int* in_sizes, int n_in,
                              void* d_out, int out_size)
{
    const float* x      = (const float*)d_in[0];
    const float* enc_k  = (const float*)d_in[1];
    const float* enc_v  = (const float*)d_in[2];
    const float* qkv_w  = (const float*)d_in[3];
    const float* qkv_b  = (const float*)d_in[4];
    const float* proj_w = (const float*)d_in[5];
    const float* proj_b = (const float*)d_in[6];
    float* out = (float*)d_out;
    float* loss_ptr = out + (out_size - 1);

    __nv_bfloat16 *xh, *xl, *wqh, *wql, *wph, *wpl, *oh, *ol;
    cudaGetSymbolAddress((void**)&xh,  g_xh);   cudaGetSymbolAddress((void**)&xl,  g_xl);
    cudaGetSymbolAddress((void**)&wqh, g_wqh);  cudaGetSymbolAddress((void**)&wql, g_wql);
    cudaGetSymbolAddress((void**)&wph, g_wph);  cudaGetSymbolAddress((void**)&wpl, g_wpl);
    cudaGetSymbolAddress((void**)&oh,  g_oh);   cudaGetSymbolAddress((void**)&ol,  g_ol);

    static bool attr_set = false;
    if (!attr_set) {
        cudaFuncSetAttribute(attn_kernel,
                             cudaFuncAttributeMaxDynamicSharedMemorySize, AT_SMEM_BYTES);
        cudaFuncSetAttribute(gemm_mma_kernel<0>,
                             cudaFuncAttributeMaxDynamicSharedMemorySize, GM_SMEM_BYTES);
        cudaFuncSetAttribute(gemm_mma_kernel<1>,
                             cudaFuncAttributeMaxDynamicSharedMemorySize, GM_SMEM_BYTES);
        attr_set = true;
    }

    cudaMemsetAsync(loss_ptr, 0, sizeof(float));

    // 0) fused fp32 -> bf16 hi/lo splits (all 5 tensors, one launch)
    split_all_kernel<<<(N4_ALL + 255) / 256, 256>>>(x, qkv_w, proj_w, enc_k, enc_v);

    // 1) QKV GEMM (tensor cores) -> head-major bf16 hi/lo Q(scaled)/K/V
    gemm_mma_kernel<1><<<dim3(QKVN / 128, ROWS / 128), 256, GM_SMEM_BYTES>>>(
        xh, xl, wqh, wql, qkv_b, nullptr, ROWS, QKVN, DIM);

    // 2) Dual attention + loss (tensor cores, FA2 register P) -> g_oh/g_ol
    attn_kernel<<<dim3(SEQ / 128, BATCH * HEADS), 256, AT_SMEM_BYTES>>>(loss_ptr);

    // 3) proj GEMM (tensor cores) -> out
    gemm_mma_kernel<0><<<dim3(DIM / 128, ROWS / 128), 256, GM_SMEM_BYTES>>>(
        oh, ol, wph, wpl, proj_b, out, ROWS, DIM, DIM);
}

// round 14
// speedup vs baseline: 1.2758x; 1.0636x over previous
#include <cuda_runtime.h>
#include <cuda_bf16.h>
#include <cstdint>
#include <cstddef>

// Problem constants (fixed by setup_inputs)
#define BATCH 4
#define SEQ   1024
#define DIM   1152
#define HEADS 16
#define HDIM  72
#define ROWS  (BATCH*SEQ)          // 4096
#define QKVN  (3*DIM)              // 3456
#define TOTAL_ELEMS 4718592.0f     // B*H*N*hd for loss mean
#define QSCALE 0.11785113f         // 72^-0.5

// Scratch (static device allocation — allowed). All bf16 hi/lo pairs.
__device__ __align__(16) __nv_bfloat16 g_xh [(size_t)ROWS * DIM];
__device__ __align__(16) __nv_bfloat16 g_xl [(size_t)ROWS * DIM];
__device__ __align__(16) __nv_bfloat16 g_wqh[(size_t)QKVN * DIM];
__device__ __align__(16) __nv_bfloat16 g_wql[(size_t)QKVN * DIM];
__device__ __align__(16) __nv_bfloat16 g_wph[(size_t)DIM * DIM];
__device__ __align__(16) __nv_bfloat16 g_wpl[(size_t)DIM * DIM];
// head-major [bh][seq][72] bf16 Q/K/V (hi/lo), written by QKV GEMM epilogue
__device__ __align__(16) __nv_bfloat16 g_qh [(size_t)ROWS * DIM];
__device__ __align__(16) __nv_bfloat16 g_ql [(size_t)ROWS * DIM];
__device__ __align__(16) __nv_bfloat16 g_kh [(size_t)ROWS * DIM];
__device__ __align__(16) __nv_bfloat16 g_kl [(size_t)ROWS * DIM];
__device__ __align__(16) __nv_bfloat16 g_vh [(size_t)ROWS * DIM];
__device__ __align__(16) __nv_bfloat16 g_vl [(size_t)ROWS * DIM];
// encoder K/V pre-split (same [bh][seq][72] layout as the fp32 inputs)
__device__ __align__(16) __nv_bfloat16 g_ekh[(size_t)ROWS * DIM];
__device__ __align__(16) __nv_bfloat16 g_ekl[(size_t)ROWS * DIM];
__device__ __align__(16) __nv_bfloat16 g_evh[(size_t)ROWS * DIM];
__device__ __align__(16) __nv_bfloat16 g_evl[(size_t)ROWS * DIM];
// attention output (hi/lo) -> proj GEMM input
__device__ __align__(16) __nv_bfloat16 g_oh [(size_t)ROWS * DIM];
__device__ __align__(16) __nv_bfloat16 g_ol [(size_t)ROWS * DIM];

extern __shared__ char dynsm[];

// ---------------------------------------------------------------------------
// helpers
// ---------------------------------------------------------------------------
__device__ __forceinline__ void cp16(uint32_t dst, const void* src) {
    asm volatile("cp.async.cg.shared.global [%0], [%1], 16;" :: "r"(dst), "l"(src));
}
__device__ __forceinline__ void mma_bf16(float* d, const uint32_t* a, const uint32_t* b) {
    asm volatile(
        "mma.sync.aligned.m16n8k16.row.col.f32.bf16.bf16.f32 "
        "{%0,%1,%2,%3}, {%4,%5,%6,%7}, {%8,%9}, {%0,%1,%2,%3};"
        : "+f"(d[0]), "+f"(d[1]), "+f"(d[2]), "+f"(d[3])
        : "r"(a[0]), "r"(a[1]), "r"(a[2]), "r"(a[3]), "r"(b[0]), "r"(b[1]));
}
__device__ __forceinline__ void ldsm_x2_trans(uint32_t& r0, uint32_t& r1, uint32_t saddr) {
    asm volatile("ldmatrix.sync.aligned.m8n8.x2.trans.shared.b16 {%0,%1}, [%2];"
                 : "=r"(r0), "=r"(r1) : "r"(saddr));
}
__device__ __forceinline__ void ldsm_x4_trans(uint32_t& r0, uint32_t& r1,
                                              uint32_t& r2, uint32_t& r3, uint32_t saddr) {
    asm volatile("ldmatrix.sync.aligned.m8n8.x4.trans.shared.b16 {%0,%1,%2,%3}, [%4];"
                 : "=r"(r0), "=r"(r1), "=r"(r2), "=r"(r3) : "r"(saddr));
}
__device__ __forceinline__ void ldsm_x4(uint32_t& r0, uint32_t& r1,
                                        uint32_t& r2, uint32_t& r3, uint32_t saddr) {
    asm volatile("ldmatrix.sync.aligned.m8n8.x4.shared.b16 {%0,%1,%2,%3}, [%4];"
                 : "=r"(r0), "=r"(r1), "=r"(r2), "=r"(r3) : "r"(saddr));
}
__device__ __forceinline__ void split2(float x, float y, uint32_t& h, uint32_t& l) {
    __nv_bfloat16 h0 = __float2bfloat16(x);
    __nv_bfloat16 h1 = __float2bfloat16(y);
    __nv_bfloat16 l0 = __float2bfloat16(x - __bfloat162float(h0));
    __nv_bfloat16 l1 = __float2bfloat16(y - __bfloat162float(h1));
    __nv_bfloat162 hh; hh.x = h0; hh.y = h1;
    __nv_bfloat162 ll; ll.x = l0; ll.y = l1;
    h = *(uint32_t*)&hh;
    l = *(uint32_t*)&ll;
}
__device__ __forceinline__ float2 unsplit(uint32_t h, uint32_t l) {
    __nv_bfloat162 hh = *(__nv_bfloat162*)&h;
    __nv_bfloat162 ll = *(__nv_bfloat162*)&l;
    return make_float2(__bfloat162float(hh.x) + __bfloat162float(ll.x),
                       __bfloat162float(hh.y) + __bfloat162float(ll.y));
}

// ---------------------------------------------------------------------------
// Fused fp32 -> bf16 (hi, lo) split over all 5 input tensors (one launch).
// ---------------------------------------------------------------------------
#define N4_X  ((ROWS * DIM) / 4)
#define N4_WQ ((QKVN * DIM) / 4)
#define N4_WP ((DIM * DIM) / 4)
#define N4_ALL (N4_X + N4_WQ + N4_WP + N4_X + N4_X)

__global__ __launch_bounds__(256)
void split_all_kernel(const float* __restrict__ x,    const float* __restrict__ wq,
                      const float* __restrict__ wp,   const float* __restrict__ ek,
                      const float* __restrict__ ev)
{
    int i = blockIdx.x * 256 + threadIdx.x;
    if (i >= N4_ALL) return;
    const float* src;
    __nv_bfloat16 *hi, *lo;
    int o = i;
    if (o < N4_X)                   { src = x;  hi = g_xh;  lo = g_xl;  }
    else if ((o -= N4_X) < N4_WQ)   { src = wq; hi = g_wqh; lo = g_wql; }
    else if ((o -= N4_WQ) < N4_WP)  { src = wp; hi = g_wph; lo = g_wpl; }
    else if ((o -= N4_WP) < N4_X)   { src = ek; hi = g_ekh; lo = g_ekl; }
    else                            { o -= N4_X; src = ev; hi = g_evh; lo = g_evl; }

    float4 v = ((const float4*)src)[o];
    uint32_t h0, l0, h1, l1;
    split2(v.x, v.y, h0, l0);
    split2(v.z, v.w, h1, l1);
    ((uint32_t*)hi)[2 * o]     = h0;
    ((uint32_t*)hi)[2 * o + 1] = h1;
    ((uint32_t*)lo)[2 * o]     = l0;
    ((uint32_t*)lo)[2 * o + 1] = l1;
}

// ---------------------------------------------------------------------------
// Tensor-core GEMM (3-term bf16 split), ldmatrix.x4 fragment loads.
// EPI=0: fp32 C (+bias). EPI=1: QKV epilogue (head-major bf16 hi/lo).
// smem per stage: Ah@0, Al@10240, Bh@20480, Bl@30720 ([128][40] bf16 each).
// ---------------------------------------------------------------------------
#define GM_SMEM_BYTES 81920

template<int EPI>
__global__ __launch_bounds__(256, 2)
void gemm_mma_kernel(const __nv_bfloat16* __restrict__ Ah, const __nv_bfloat16* __restrict__ Al,
                     const __nv_bfloat16* __restrict__ Bh, const __nv_bfloat16* __restrict__ Bl,
                     const float* __restrict__ bias, float* __restrict__ C,
                     int M, int N, int K)
{
    const uint32_t sb32 = (uint32_t)__cvta_generic_to_shared(dynsm);

    const int tid  = threadIdx.x;
    const int warp = tid >> 5, lane = tid & 31;
    const int wm = warp >> 2, wn = warp & 3;
    const int gr = lane >> 2, c4 = lane & 3;
    const int m0 = blockIdx.y * 128, n0 = blockIdx.x * 128;

    const int l_row0 = tid >> 2,            l_cb0 = (tid & 3) << 3;
    const int l_row1 = (tid + 256) >> 2,    l_cb1 = ((tid + 256) & 3) << 3;

    // ldmatrix per-lane address components (element offsets within a stage array)
    const int a_row = (lane & 15);              // + wm*64 + i*16
    const int a_kc  = (lane >> 4) * 8;          // + ks*16
    const int b_row = (lane & 7) + ((lane >> 4) & 1) * 8;   // + wn*32 + jp*16
    const int b_kc  = ((lane >> 3) & 1) * 8;    // + ks*16

    float acc[4][4][4];
#pragma unroll
    for (int i = 0; i < 4; i++)
#pragma unroll
        for (int j = 0; j < 4; j++)
#pragma unroll
            for (int r = 0; r < 4; r++) acc[i][j][r] = 0.f;

    const int nkt = K >> 5;

    auto load_tile = [&](int stage, int kt) {
        const int k0 = kt << 5;
        const uint32_t st = sb32 + stage * 40960u;
        cp16(st + (uint32_t)(l_row0 * 80 + l_cb0 * 2),
             Ah + (size_t)(m0 + l_row0) * K + k0 + l_cb0);
        cp16(st + (uint32_t)(l_row1 * 80 + l_cb1 * 2),
             Ah + (size_t)(m0 + l_row1) * K + k0 + l_cb1);
        cp16(st + 10240u + (uint32_t)(l_row0 * 80 + l_cb0 * 2),
             Al + (size_t)(m0 + l_row0) * K + k0 + l_cb0);
        cp16(st + 10240u + (uint32_t)(l_row1 * 80 + l_cb1 * 2),
             Al + (size_t)(m0 + l_row1) * K + k0 + l_cb1);
        cp16(st + 20480u + (uint32_t)(l_row0 * 80 + l_cb0 * 2),
             Bh + (size_t)(n0 + l_row0) * K + k0 + l_cb0);
        cp16(st + 20480u + (uint32_t)(l_row1 * 80 + l_cb1 * 2),
             Bh + (size_t)(n0 + l_row1) * K + k0 + l_cb1);
        cp16(st + 30720u + (uint32_t)(l_row0 * 80 + l_cb0 * 2),
             Bl + (size_t)(n0 + l_row0) * K + k0 + l_cb0);
        cp16(st + 30720u + (uint32_t)(l_row1 * 80 + l_cb1 * 2),
             Bl + (size_t)(n0 + l_row1) * K + k0 + l_cb1);
        asm volatile("cp.async.commit_group;");
    };

    load_tile(0, 0);
    load_tile(1, 1);

    for (int kt = 0; kt < nkt; kt++) {
        if (kt + 1 < nkt) asm volatile("cp.async.wait_group 1;");
        else              asm volatile("cp.async.wait_group 0;");
        __syncthreads();

        const uint32_t st = sb32 + (kt & 1) * 40960u;

#pragma unroll
        for (int ks = 0; ks < 2; ks++) {
            uint32_t bh[4][2], bl[4][2];
#pragma unroll
            for (int jp = 0; jp < 2; jp++) {
                const uint32_t ba = st + 20480u +
                    (uint32_t)((wn * 32 + jp * 16 + b_row) * 80 +
                               (ks * 16 + b_kc) * 2);
                ldsm_x4(bh[2*jp][0], bh[2*jp][1], bh[2*jp+1][0], bh[2*jp+1][1], ba);
                ldsm_x4(bl[2*jp][0], bl[2*jp][1], bl[2*jp+1][0], bl[2*jp+1][1], ba + 10240u);
            }
#pragma unroll
            for (int i = 0; i < 4; i++) {
                const uint32_t aa = st +
                    (uint32_t)((wm * 64 + i * 16 + a_row) * 80 +
                               (ks * 16 + a_kc) * 2);
                uint32_t ah[4], al[4];
                ldsm_x4(ah[0], ah[1], ah[2], ah[3], aa);
                ldsm_x4(al[0], al[1], al[2], al[3], aa + 10240u);
#pragma unroll
                for (int j = 0; j < 4; j++) {
                    mma_bf16(acc[i][j], ah, bh[j]);
                    mma_bf16(acc[i][j], ah, bl[j]);
                    mma_bf16(acc[i][j], al, bh[j]);
                }
            }
        }
        __syncthreads();
        if (kt + 2 < nkt) load_tile(kt & 1, kt + 2);
    }

#pragma unroll
    for (int j = 0; j < 4; j++) {
        const int gn = n0 + wn * 32 + j * 8 + 2 * c4;
        const float b0 = bias[gn], b1 = bias[gn + 1];
        if (EPI == 0) {
#pragma unroll
            for (int i = 0; i < 4; i++) {
                const int gm = m0 + wm * 64 + i * 16 + gr;
                float2 w0, w1;
                w0.x = acc[i][j][0] + b0; w0.y = acc[i][j][1] + b1;
                w1.x = acc[i][j][2] + b0; w1.y = acc[i][j][3] + b1;
                *(float2*)&C[(size_t)gm * N + gn] = w0;
                *(float2*)&C[(size_t)(gm + 8) * N + gn] = w1;
            }
        } else {
            const int part = gn / DIM;
            const int rem  = gn - part * DIM;
            const int hh   = rem / HDIM;
            const int dd   = rem - hh * HDIM;          // even
            uint32_t* dsth;
            uint32_t* dstl;
            float sc = 1.f;
            if (part == 0)      { dsth = (uint32_t*)g_qh; dstl = (uint32_t*)g_ql; sc = QSCALE; }
            else if (part == 1) { dsth = (uint32_t*)g_kh; dstl = (uint32_t*)g_kl; }
            else                { dsth = (uint32_t*)g_vh; dstl = (uint32_t*)g_vl; }
#pragma unroll
            for (int i = 0; i < 4; i++) {
                const int gm = m0 + wm * 64 + i * 16 + gr;
                const int b_ = gm >> 10, seq = gm & 1023;
                const size_t idx = (((size_t)(b_ * HEADS + hh) << 10) + seq) * 36 + (dd >> 1);
                uint32_t h_, l_;
                split2((acc[i][j][0] + b0) * sc, (acc[i][j][1] + b1) * sc, h_, l_);
                dsth[idx] = h_; dstl[idx] = l_;
                split2((acc[i][j][2] + b0) * sc, (acc[i][j][3] + b1) * sc, h_, l_);
                dsth[idx + 8 * 36] = h_; dstl[idx + 8 * 36] = l_;
            }
        }
    }
}

// ---------------------------------------------------------------------------
// Attention v8 (FA2 register P; ldmatrix.x4 for Q, K, V fragments).
// 128-query tile, 256 threads (8 warps), warp owns 16 query rows.
// smem: sQh @0, sQl @22528 B (each [128][88] bf16); KV @45056 B:
// 2 bufs x {Kh,Kl,Vh,Vl} ([64][88] bf16, 11264 B each). Total 135168 B.
// ---------------------------------------------------------------------------
#define AT_SMEM_BYTES 135168

__global__ __launch_bounds__(256)
void attn_kernel(float* __restrict__ loss_out)
{
    __nv_bfloat16* smbf = (__nv_bfloat16*)dynsm;

    const uint32_t smu   = (uint32_t)__cvta_generic_to_shared(smbf);
    const uint32_t kvb32 = smu + 45056u;

    const int tid  = threadIdx.x;
    const int warp = tid >> 5, lane = tid & 31;
    const int gr = lane >> 2, c4 = lane & 3;

    const int bh = blockIdx.y, b = bh >> 4, h = bh & 15;
    const int n0 = blockIdx.x * 128;

    // ldmatrix per-lane address components
    const int a_row = (lane & 15);                           // A (Q): + warp*16
    const int a_kc  = (lane >> 4) * 8;                       // + ks*16
    const int b_row = (lane & 7) + ((lane >> 4) & 1) * 8;    // B (K): + jp*16
    const int b_kc  = ((lane >> 3) & 1) * 8;                 // + ks*16

    auto prefetch = [&](int t, int buf) {
        const int kt = t & 15;
        const __nv_bfloat16* s0 = (t < 16) ? g_kh : g_ekh;
        const __nv_bfloat16* s1 = (t < 16) ? g_kl : g_ekl;
        const __nv_bfloat16* s2 = (t < 16) ? g_vh : g_evh;
        const __nv_bfloat16* s3 = (t < 16) ? g_vl : g_evl;
        const size_t toff = (((size_t)bh << 10) + kt * 64) * HDIM;
#pragma unroll
        for (int r = 0; r < 9; r++) {
            int e = tid + r * 256;
            int arr = e / 576, rem = e - arr * 576;
            int row = rem / 9,  ch  = rem - row * 9;
            const __nv_bfloat16* src =
                (arr == 0 ? s0 : arr == 1 ? s1 : arr == 2 ? s2 : s3)
                + toff + row * HDIM + ch * 8;
            cp16(kvb32 + buf * 45056u + arr * 11264u
                       + (uint32_t)(row * 176 + ch * 16), src);
        }
        asm volatile("cp.async.commit_group;");
    };
    prefetch(0, 0);

    // zero pads (cols 72..87)
    for (int i = tid; i < 2048; i += 256) {
        int arr = i >> 10, rem = i & 1023;
        int row = rem >> 3, cp = rem & 7;
        *(uint32_t*)(smbf + arr * 11264 + row * 88 + 72 + 2 * cp) = 0;
    }
    for (int i = tid; i < 4096; i += 256) {
        int arr = i >> 9, rem = i & 511;
        int row = rem >> 3, cp = rem & 7;
        *(uint32_t*)(smbf + 22528 + arr * 5632 + row * 88 + 72 + 2 * cp) = 0;
    }

    // load Q tile
    {
        const uint32_t* qh = (const uint32_t*)g_qh;
        const uint32_t* ql = (const uint32_t*)g_ql;
        const size_t qoff = (((size_t)bh << 10) + n0) * 36;
#pragma unroll
        for (int r = 0; r < 18; r++) {
            int e = tid + r * 256;
            int row = e / 36, ch = e - row * 36;
            size_t gi = qoff + row * 36 + ch;
            *(uint32_t*)(smbf + row * 88 + ch * 2) = qh[gi];
            *(uint32_t*)(smbf + 11264 + row * 88 + ch * 2) = ql[gi];
        }
    }

    float lsum = 0.f;
    float m0 = -1e30f, m1 = -1e30f, l0 = 0.f, l1 = 0.f;
    float oacc[9][4];
#pragma unroll
    for (int j = 0; j < 9; j++)
#pragma unroll
        for (int r = 0; r < 4; r++) oacc[j][r] = 0.f;

    const int qrow = warp * 16 + gr;

#pragma unroll 1
    for (int t = 0; t < 32; t++) {
        const int buf = t & 1;

        asm volatile("cp.async.wait_group 0;");
        __syncthreads();
        if (t + 1 < 32) prefetch(t + 1, buf ^ 1);

        const uint32_t kh_base = kvb32 + buf * 45056u;            // sKh bytes
        const uint32_t vh_base = kh_base + 22528u;                // sVh bytes

        // ---- scores: ldmatrix.x4 Q and K fragments ----
        float sacc[8][4];
#pragma unroll
        for (int j = 0; j < 8; j++)
#pragma unroll
            for (int r = 0; r < 4; r++) sacc[j][r] = 0.f;

#pragma unroll
        for (int ks = 0; ks < 5; ks++) {
            const uint32_t qa = smu +
                (uint32_t)((warp * 16 + a_row) * 176 + (ks * 16 + a_kc) * 2);
            uint32_t ah[4], al[4];
            ldsm_x4(ah[0], ah[1], ah[2], ah[3], qa);
            ldsm_x4(al[0], al[1], al[2], al[3], qa + 22528u);
#pragma unroll
            for (int jp = 0; jp < 4; jp++) {
                const uint32_t ka = kh_base +
                    (uint32_t)((jp * 16 + b_row) * 176 + (ks * 16 + b_kc) * 2);
                uint32_t kh4[4], kl4[4];
                ldsm_x4(kh4[0], kh4[1], kh4[2], kh4[3], ka);
                ldsm_x4(kl4[0], kl4[1], kl4[2], kl4[3], ka + 11264u);
                mma_bf16(sacc[2*jp],     ah, kh4);
                mma_bf16(sacc[2*jp],     ah, kl4);
                mma_bf16(sacc[2*jp],     al, kh4);
                mma_bf16(sacc[2*jp + 1], ah, kh4 + 2);
                mma_bf16(sacc[2*jp + 1], ah, kl4 + 2);
                mma_bf16(sacc[2*jp + 1], al, kh4 + 2);
            }
        }

        // ---- online softmax in registers ----
        {
            float t0 = -1e30f, t1 = -1e30f;
#pragma unroll
            for (int j = 0; j < 8; j++) {
                t0 = fmaxf(t0, fmaxf(sacc[j][0], sacc[j][1]));
                t1 = fmaxf(t1, fmaxf(sacc[j][2], sacc[j][3]));
            }
            t0 = fmaxf(t0, __shfl_xor_sync(0xffffffffu, t0, 1));
            t0 = fmaxf(t0, __shfl_xor_sync(0xffffffffu, t0, 2));
            t1 = fmaxf(t1, __shfl_xor_sync(0xffffffffu, t1, 1));
            t1 = fmaxf(t1, __shfl_xor_sync(0xffffffffu, t1, 2));
            const float nm0 = fmaxf(m0, t0), nm1 = fmaxf(m1, t1);
            const float cr0 = __expf(m0 - nm0), cr1 = __expf(m1 - nm1);
            float s0 = 0.f, s1 = 0.f;
#pragma unroll
            for (int j = 0; j < 8; j++) {
                sacc[j][0] = __expf(sacc[j][0] - nm0);
                sacc[j][1] = __expf(sacc[j][1] - nm0);
                sacc[j][2] = __expf(sacc[j][2] - nm1);
                sacc[j][3] = __expf(sacc[j][3] - nm1);
                s0 += sacc[j][0] + sacc[j][1];
                s1 += sacc[j][2] + sacc[j][3];
            }
            s0 += __shfl_xor_sync(0xffffffffu, s0, 1);
            s0 += __shfl_xor_sync(0xffffffffu, s0, 2);
            s1 += __shfl_xor_sync(0xffffffffu, s1, 1);
            s1 += __shfl_xor_sync(0xffffffffu, s1, 2);
            l0 = l0 * cr0 + s0; l1 = l1 * cr1 + s1;
            m0 = nm0; m1 = nm1;
#pragma unroll
            for (int j = 0; j < 9; j++) {
                oacc[j][0] *= cr0; oacc[j][1] *= cr0;
                oacc[j][2] *= cr1; oacc[j][3] *= cr1;
            }
        }

        // ---- PV: register P fragments; V via ldmatrix.x4.trans ----
#pragma unroll
        for (int ks = 0; ks < 4; ks++) {
            uint32_t ph[4], pl[4];
            split2(sacc[2*ks][0],   sacc[2*ks][1],   ph[0], pl[0]);
            split2(sacc[2*ks][2],   sacc[2*ks][3],   ph[1], pl[1]);
            split2(sacc[2*ks+1][0], sacc[2*ks+1][1], ph[2], pl[2]);
            split2(sacc[2*ks+1][2], sacc[2*ks+1][3], ph[3], pl[3]);
            const uint32_t va_base = vh_base +
                (uint32_t)(((ks * 16 + (lane & 15)) * 88) * 2) +
                (uint32_t)((lane >> 4) * 16);
#pragma unroll
            for (int jp = 0; jp < 8; jp += 2) {
                const uint32_t va = va_base + (uint32_t)(jp * 16);
                uint32_t vh4[4], vl4[4];
                ldsm_x4_trans(vh4[0], vh4[1], vh4[2], vh4[3], va);
                ldsm_x4_trans(vl4[0], vl4[1], vl4[2], vl4[3], va + 11264u);
                mma_bf16(oacc[jp],     ph, vh4);
                mma_bf16(oacc[jp],     ph, vl4);
                mma_bf16(oacc[jp],     pl, vh4);
                mma_bf16(oacc[jp + 1], ph, vh4 + 2);
                mma_bf16(oacc[jp + 1], ph, vl4 + 2);
                mma_bf16(oacc[jp + 1], pl, vh4 + 2);
            }
            {   // j = 8 remainder
                const uint32_t va = vh_base +
                    (uint32_t)(((ks * 16 + (lane & 15)) * 88) * 2) +
                    (uint32_t)(8 * 16);
                uint32_t vh2[2], vl2[2];
                ldsm_x2_trans(vh2[0], vh2[1], va);
                ldsm_x2_trans(vl2[0], vl2[1], va + 11264u);
                mma_bf16(oacc[8], ph, vh2);
                mma_bf16(oacc[8], ph, vl2);
                mma_bf16(oacc[8], pl, vh2);
            }
        }

        // ---- pass epilogues ----
        if (t == 15) {
            const float i0 = 1.0f / l0, i1 = 1.0f / l1;
            const int q0 = n0 + qrow;
            uint32_t* dh = (uint32_t*)g_oh;
            uint32_t* dl = (uint32_t*)g_ol;
#pragma unroll
            for (int j = 0; j < 9; j++) {
                const int dim = j * 8 + 2 * c4;
                const size_t i0x = (((size_t)(b * SEQ + q0)) * DIM
                                    + h * HDIM + dim) >> 1;
                const size_t i1x = (((size_t)(b * SEQ + q0 + 8)) * DIM
                                    + h * HDIM + dim) >> 1;
                uint32_t hh, ll;
                split2(oacc[j][0] * i0, oacc[j][1] * i0, hh, ll);
                dh[i0x] = hh; dl[i0x] = ll;
                split2(oacc[j][2] * i1, oacc[j][3] * i1, hh, ll);
                dh[i1x] = hh; dl[i1x] = ll;
            }
            m0 = -1e30f; m1 = -1e30f; l0 = 0.f; l1 = 0.f;
#pragma unroll
            for (int j = 0; j < 9; j++)
#pragma unroll
                for (int r = 0; r < 4; r++) oacc[j][r] = 0.f;
        } else if (t == 31) {
            const float i0 = 1.0f / l0, i1 = 1.0f / l1;
            const int q0 = n0 + qrow;
            const uint32_t* dh = (const uint32_t*)g_oh;
            const uint32_t* dl = (const uint32_t*)g_ol;
#pragma unroll
            for (int j = 0; j < 9; j++) {
                const int dim = j * 8 + 2 * c4;
                const size_t i0x = (((size_t)(b * SEQ + q0)) * DIM
                                    + h * HDIM + dim) >> 1;
                const size_t i1x = (((size_t)(b * SEQ + q0 + 8)) * DIM
                                    + h * HDIM + dim) >> 1;
                float2 x0 = unsplit(dh[i0x], dl[i0x]);
                float2 x1 = unsplit(dh[i1x], dl[i1x]);
                float e0 = x0.x - oacc[j][0] * i0;
                float e1 = x0.y - oacc[j][1] * i0;
                float e2 = x1.x - oacc[j][2] * i1;
                float e3 = x1.y - oacc[j][3] * i1;
                lsum += e0*e0 + e1*e1 + e2*e2 + e3*e3;
            }
        }
    }

    lsum *= (1.0f / TOTAL_ELEMS);
#pragma unroll
    for (int o = 16; o > 0; o >>= 1)
        lsum += __shfl_down_sync(0xffffffffu, lsum, o);
    if (lane == 0) atomicAdd(loss_out, lsum);
}

// ---------------------------------------------------------------------------
extern "C" void kernel_launch(void* const* d_in, const int* in_sizes, int n_in,
                              void* d_out, int out_size)
{
    const float* x      = (const float*)d_in[0];
    const float* enc_k  = (const float*)d_in[1];
    const float* enc_v  = (const float*)d_in[2];
    const float* qkv_w  = (const float*)d_in[3];
    const float* qkv_b  = (const float*)d_in[4];
    const float* proj_w = (const float*)d_in[5];
    const float* proj_b = (const float*)d_in[6];
    float* out = (float*)d_out;
    float* loss_ptr = out + (out_size - 1);

    __nv_bfloat16 *xh, *xl, *wqh, *wql, *wph, *wpl, *oh, *ol;
    cudaGetSymbolAddress((void**)&xh,  g_xh);   cudaGetSymbolAddress((void**)&xl,  g_xl);
    cudaGetSymbolAddress((void**)&wqh, g_wqh);  cudaGetSymbolAddress((void**)&wql, g_wql);
    cudaGetSymbolAddress((void**)&wph, g_wph);  cudaGetSymbolAddress((void**)&wpl, g_wpl);
    cudaGetSymbolAddress((void**)&oh,  g_oh);   cudaGetSymbolAddress((void**)&ol,  g_ol);

    static bool attr_set = false;
    if (!attr_set) {
        cudaFuncSetAttribute(attn_kernel,
                             cudaFuncAttributeMaxDynamicSharedMemorySize, AT_SMEM_BYTES);
        cudaFuncSetAttribute(gemm_mma_kernel<0>,
                             cudaFuncAttributeMaxDynamicSharedMemorySize, GM_SMEM_BYTES);
        cudaFuncSetAttribute(gemm_mma_kernel<1>,
                             cudaFuncAttributeMaxDynamicSharedMemorySize, GM_SMEM_BYTES);
        attr_set = true;
    }

    cudaMemsetAsync(loss_ptr, 0, sizeof(float));

    // 0) fused fp32 -> bf16 hi/lo splits (all 5 tensors, one launch)
    split_all_kernel<<<(N4_ALL + 255) / 256, 256>>>(x, qkv_w, proj_w, enc_k, enc_v);

    // 1) QKV GEMM (tensor cores) -> head-major bf16 hi/lo Q(scaled)/K/V
    gemm_mma_kernel<1><<<dim3(QKVN / 128, ROWS / 128), 256, GM_SMEM_BYTES>>>(
        xh, xl, wqh, wql, qkv_b, nullptr, ROWS, QKVN, DIM);

    // 2) Dual attention + loss (tensor cores, FA2 register P) -> g_oh/g_ol
    attn_kernel<<<dim3(SEQ / 128, BATCH * HEADS), 256, AT_SMEM_BYTES>>>(loss_ptr);

    // 3) proj GEMM (tensor cores) -> out
    gemm_mma_kernel<0><<<dim3(DIM / 128, ROWS / 128), 256, GM_SMEM_BYTES>>>(
        oh, ol, wph, wpl, proj_b, out, ROWS, DIM, DIM);
}

// round 15
// speedup vs baseline: 1.3190x; 1.0338x over previous
#include <cuda_runtime.h>
#include <cuda_bf16.h>
#include <cstdint>
#include <cstddef>

// Problem constants (fixed by setup_inputs)
#define BATCH 4
#define SEQ   1024
#define DIM   1152
#define HEADS 16
#define HDIM  72
#define ROWS  (BATCH*SEQ)          // 4096
#define QKVN  (3*DIM)              // 3456
#define TOTAL_ELEMS 4718592.0f     // B*H*N*hd for loss mean
#define QSCALE 0.11785113f         // 72^-0.5

// Scratch (static device allocation — allowed). All bf16 hi/lo pairs.
__device__ __align__(16) __nv_bfloat16 g_xh [(size_t)ROWS * DIM];
__device__ __align__(16) __nv_bfloat16 g_xl [(size_t)ROWS * DIM];
__device__ __align__(16) __nv_bfloat16 g_wqh[(size_t)QKVN * DIM];
__device__ __align__(16) __nv_bfloat16 g_wql[(size_t)QKVN * DIM];
__device__ __align__(16) __nv_bfloat16 g_wph[(size_t)DIM * DIM];
__device__ __align__(16) __nv_bfloat16 g_wpl[(size_t)DIM * DIM];
// head-major [bh][seq][72] bf16 Q/K/V (hi/lo), written by QKV GEMM epilogue
__device__ __align__(16) __nv_bfloat16 g_qh [(size_t)ROWS * DIM];
__device__ __align__(16) __nv_bfloat16 g_ql [(size_t)ROWS * DIM];
__device__ __align__(16) __nv_bfloat16 g_kh [(size_t)ROWS * DIM];
__device__ __align__(16) __nv_bfloat16 g_kl [(size_t)ROWS * DIM];
__device__ __align__(16) __nv_bfloat16 g_vh [(size_t)ROWS * DIM];
__device__ __align__(16) __nv_bfloat16 g_vl [(size_t)ROWS * DIM];
// encoder K/V pre-split (same [bh][seq][72] layout as the fp32 inputs)
__device__ __align__(16) __nv_bfloat16 g_ekh[(size_t)ROWS * DIM];
__device__ __align__(16) __nv_bfloat16 g_ekl[(size_t)ROWS * DIM];
__device__ __align__(16) __nv_bfloat16 g_evh[(size_t)ROWS * DIM];
__device__ __align__(16) __nv_bfloat16 g_evl[(size_t)ROWS * DIM];
// attention output (hi/lo) -> proj GEMM input
__device__ __align__(16) __nv_bfloat16 g_oh [(size_t)ROWS * DIM];
__device__ __align__(16) __nv_bfloat16 g_ol [(size_t)ROWS * DIM];

extern __shared__ char dynsm[];

// ---------------------------------------------------------------------------
// helpers
// ---------------------------------------------------------------------------
__device__ __forceinline__ void cp16(uint32_t dst, const void* src) {
    asm volatile("cp.async.cg.shared.global [%0], [%1], 16;" :: "r"(dst), "l"(src));
}
__device__ __forceinline__ void mma_bf16(float* d, const uint32_t* a, const uint32_t* b) {
    asm volatile(
        "mma.sync.aligned.m16n8k16.row.col.f32.bf16.bf16.f32 "
        "{%0,%1,%2,%3}, {%4,%5,%6,%7}, {%8,%9}, {%0,%1,%2,%3};"
        : "+f"(d[0]), "+f"(d[1]), "+f"(d[2]), "+f"(d[3])
        : "r"(a[0]), "r"(a[1]), "r"(a[2]), "r"(a[3]), "r"(b[0]), "r"(b[1]));
}
__device__ __forceinline__ void ldsm_x2_trans(uint32_t& r0, uint32_t& r1, uint32_t saddr) {
    asm volatile("ldmatrix.sync.aligned.m8n8.x2.trans.shared.b16 {%0,%1}, [%2];"
                 : "=r"(r0), "=r"(r1) : "r"(saddr));
}
__device__ __forceinline__ void ldsm_x4_trans(uint32_t& r0, uint32_t& r1,
                                              uint32_t& r2, uint32_t& r3, uint32_t saddr) {
    asm volatile("ldmatrix.sync.aligned.m8n8.x4.trans.shared.b16 {%0,%1,%2,%3}, [%4];"
                 : "=r"(r0), "=r"(r1), "=r"(r2), "=r"(r3) : "r"(saddr));
}
__device__ __forceinline__ void ldsm_x4(uint32_t& r0, uint32_t& r1,
                                        uint32_t& r2, uint32_t& r3, uint32_t saddr) {
    asm volatile("ldmatrix.sync.aligned.m8n8.x4.shared.b16 {%0,%1,%2,%3}, [%4];"
                 : "=r"(r0), "=r"(r1), "=r"(r2), "=r"(r3) : "r"(saddr));
}
__device__ __forceinline__ void split2(float x, float y, uint32_t& h, uint32_t& l) {
    __nv_bfloat16 h0 = __float2bfloat16(x);
    __nv_bfloat16 h1 = __float2bfloat16(y);
    __nv_bfloat16 l0 = __float2bfloat16(x - __bfloat162float(h0));
    __nv_bfloat16 l1 = __float2bfloat16(y - __bfloat162float(h1));
    __nv_bfloat162 hh; hh.x = h0; hh.y = h1;
    __nv_bfloat162 ll; ll.x = l0; ll.y = l1;
    h = *(uint32_t*)&hh;
    l = *(uint32_t*)&ll;
}
__device__ __forceinline__ float2 unsplit(uint32_t h, uint32_t l) {
    __nv_bfloat162 hh = *(__nv_bfloat162*)&h;
    __nv_bfloat162 ll = *(__nv_bfloat162*)&l;
    return make_float2(__bfloat162float(hh.x) + __bfloat162float(ll.x),
                       __bfloat162float(hh.y) + __bfloat162float(ll.y));
}

// ---------------------------------------------------------------------------
// Fused fp32 -> bf16 (hi, lo) split over all 5 input tensors (one launch).
// ---------------------------------------------------------------------------
#define N4_X  ((ROWS * DIM) / 4)
#define N4_WQ ((QKVN * DIM) / 4)
#define N4_WP ((DIM * DIM) / 4)
#define N4_ALL (N4_X + N4_WQ + N4_WP + N4_X + N4_X)

__global__ __launch_bounds__(256)
void split_all_kernel(const float* __restrict__ x,    const float* __restrict__ wq,
                      const float* __restrict__ wp,   const float* __restrict__ ek,
                      const float* __restrict__ ev)
{
    int i = blockIdx.x * 256 + threadIdx.x;
    if (i >= N4_ALL) return;
    const float* src;
    __nv_bfloat16 *hi, *lo;
    int o = i;
    if (o < N4_X)                   { src = x;  hi = g_xh;  lo = g_xl;  }
    else if ((o -= N4_X) < N4_WQ)   { src = wq; hi = g_wqh; lo = g_wql; }
    else if ((o -= N4_WQ) < N4_WP)  { src = wp; hi = g_wph; lo = g_wpl; }
    else if ((o -= N4_WP) < N4_X)   { src = ek; hi = g_ekh; lo = g_ekl; }
    else                            { o -= N4_X; src = ev; hi = g_evh; lo = g_evl; }

    float4 v = ((const float4*)src)[o];
    uint32_t h0, l0, h1, l1;
    split2(v.x, v.y, h0, l0);
    split2(v.z, v.w, h1, l1);
    ((uint32_t*)hi)[2 * o]     = h0;
    ((uint32_t*)hi)[2 * o + 1] = h1;
    ((uint32_t*)lo)[2 * o]     = l0;
    ((uint32_t*)lo)[2 * o + 1] = l1;
}

// ---------------------------------------------------------------------------
// Tensor-core GEMM (3-term bf16 split), ldmatrix.x4 fragment loads.
// EPI=0: fp32 C (+bias). EPI=1: QKV epilogue (head-major bf16 hi/lo).
// (Byte-identical to the 772us run.)
// ---------------------------------------------------------------------------
#define GM_SMEM_BYTES 81920

template<int EPI>
__global__ __launch_bounds__(256, 2)
void gemm_mma_kernel(const __nv_bfloat16* __restrict__ Ah, const __nv_bfloat16* __restrict__ Al,
                     const __nv_bfloat16* __restrict__ Bh, const __nv_bfloat16* __restrict__ Bl,
                     const float* __restrict__ bias, float* __restrict__ C,
                     int M, int N, int K)
{
    const uint32_t sb32 = (uint32_t)__cvta_generic_to_shared(dynsm);

    const int tid  = threadIdx.x;
    const int warp = tid >> 5, lane = tid & 31;
    const int wm = warp >> 2, wn = warp & 3;
    const int gr = lane >> 2, c4 = lane & 3;
    const int m0 = blockIdx.y * 128, n0 = blockIdx.x * 128;

    const int l_row0 = tid >> 2,            l_cb0 = (tid & 3) << 3;
    const int l_row1 = (tid + 256) >> 2,    l_cb1 = ((tid + 256) & 3) << 3;

    const int a_row = (lane & 15);
    const int a_kc  = (lane >> 4) * 8;
    const int b_row = (lane & 7) + ((lane >> 4) & 1) * 8;
    const int b_kc  = ((lane >> 3) & 1) * 8;

    float acc[4][4][4];
#pragma unroll
    for (int i = 0; i < 4; i++)
#pragma unroll
        for (int j = 0; j < 4; j++)
#pragma unroll
            for (int r = 0; r < 4; r++) acc[i][j][r] = 0.f;

    const int nkt = K >> 5;

    auto load_tile = [&](int stage, int kt) {
        const int k0 = kt << 5;
        const uint32_t st = sb32 + stage * 40960u;
        cp16(st + (uint32_t)(l_row0 * 80 + l_cb0 * 2),
             Ah + (size_t)(m0 + l_row0) * K + k0 + l_cb0);
        cp16(st + (uint32_t)(l_row1 * 80 + l_cb1 * 2),
             Ah + (size_t)(m0 + l_row1) * K + k0 + l_cb1);
        cp16(st + 10240u + (uint32_t)(l_row0 * 80 + l_cb0 * 2),
             Al + (size_t)(m0 + l_row0) * K + k0 + l_cb0);
        cp16(st + 10240u + (uint32_t)(l_row1 * 80 + l_cb1 * 2),
             Al + (size_t)(m0 + l_row1) * K + k0 + l_cb1);
        cp16(st + 20480u + (uint32_t)(l_row0 * 80 + l_cb0 * 2),
             Bh + (size_t)(n0 + l_row0) * K + k0 + l_cb0);
        cp16(st + 20480u + (uint32_t)(l_row1 * 80 + l_cb1 * 2),
             Bh + (size_t)(n0 + l_row1) * K + k0 + l_cb1);
        cp16(st + 30720u + (uint32_t)(l_row0 * 80 + l_cb0 * 2),
             Bl + (size_t)(n0 + l_row0) * K + k0 + l_cb0);
        cp16(st + 30720u + (uint32_t)(l_row1 * 80 + l_cb1 * 2),
             Bl + (size_t)(n0 + l_row1) * K + k0 + l_cb1);
        asm volatile("cp.async.commit_group;");
    };

    load_tile(0, 0);
    load_tile(1, 1);

    for (int kt = 0; kt < nkt; kt++) {
        if (kt + 1 < nkt) asm volatile("cp.async.wait_group 1;");
        else              asm volatile("cp.async.wait_group 0;");
        __syncthreads();

        const uint32_t st = sb32 + (kt & 1) * 40960u;

#pragma unroll
        for (int ks = 0; ks < 2; ks++) {
            uint32_t bh[4][2], bl[4][2];
#pragma unroll
            for (int jp = 0; jp < 2; jp++) {
                const uint32_t ba = st + 20480u +
                    (uint32_t)((wn * 32 + jp * 16 + b_row) * 80 +
                               (ks * 16 + b_kc) * 2);
                ldsm_x4(bh[2*jp][0], bh[2*jp][1], bh[2*jp+1][0], bh[2*jp+1][1], ba);
                ldsm_x4(bl[2*jp][0], bl[2*jp][1], bl[2*jp+1][0], bl[2*jp+1][1], ba + 10240u);
            }
#pragma unroll
            for (int i = 0; i < 4; i++) {
                const uint32_t aa = st +
                    (uint32_t)((wm * 64 + i * 16 + a_row) * 80 +
                               (ks * 16 + a_kc) * 2);
                uint32_t ah[4], al[4];
                ldsm_x4(ah[0], ah[1], ah[2], ah[3], aa);
                ldsm_x4(al[0], al[1], al[2], al[3], aa + 10240u);
#pragma unroll
                for (int j = 0; j < 4; j++) {
                    mma_bf16(acc[i][j], ah, bh[j]);
                    mma_bf16(acc[i][j], ah, bl[j]);
                    mma_bf16(acc[i][j], al, bh[j]);
                }
            }
        }
        __syncthreads();
        if (kt + 2 < nkt) load_tile(kt & 1, kt + 2);
    }

#pragma unroll
    for (int j = 0; j < 4; j++) {
        const int gn = n0 + wn * 32 + j * 8 + 2 * c4;
        const float b0 = bias[gn], b1 = bias[gn + 1];
        if (EPI == 0) {
#pragma unroll
            for (int i = 0; i < 4; i++) {
                const int gm = m0 + wm * 64 + i * 16 + gr;
                float2 w0, w1;
                w0.x = acc[i][j][0] + b0; w0.y = acc[i][j][1] + b1;
                w1.x = acc[i][j][2] + b0; w1.y = acc[i][j][3] + b1;
                *(float2*)&C[(size_t)gm * N + gn] = w0;
                *(float2*)&C[(size_t)(gm + 8) * N + gn] = w1;
            }
        } else {
            const int part = gn / DIM;
            const int rem  = gn - part * DIM;
            const int hh   = rem / HDIM;
            const int dd   = rem - hh * HDIM;          // even
            uint32_t* dsth;
            uint32_t* dstl;
            float sc = 1.f;
            if (part == 0)      { dsth = (uint32_t*)g_qh; dstl = (uint32_t*)g_ql; sc = QSCALE; }
            else if (part == 1) { dsth = (uint32_t*)g_kh; dstl = (uint32_t*)g_kl; }
            else                { dsth = (uint32_t*)g_vh; dstl = (uint32_t*)g_vl; }
#pragma unroll
            for (int i = 0; i < 4; i++) {
                const int gm = m0 + wm * 64 + i * 16 + gr;
                const int b_ = gm >> 10, seq = gm & 1023;
                const size_t idx = (((size_t)(b_ * HEADS + hh) << 10) + seq) * 36 + (dd >> 1);
                uint32_t h_, l_;
                split2((acc[i][j][0] + b0) * sc, (acc[i][j][1] + b1) * sc, h_, l_);
                dsth[idx] = h_; dstl[idx] = l_;
                split2((acc[i][j][2] + b0) * sc, (acc[i][j][3] + b1) * sc, h_, l_);
                dsth[idx + 8 * 36] = h_; dstl[idx + 8 * 36] = l_;
            }
        }
    }
}

// ---------------------------------------------------------------------------
// Attention v9: 256-query tile, 512 threads (16 warps, 16 q-rows each),
// FA2 register P, ldmatrix.x4 fragments, cp.async double-buffered K/V.
//
// smem (bytes):
//   sQh @0, sQl @45056                 (each [256][88] bf16 = 45056)
//   KV  @90112: 2 bufs x {Kh,Kl,Vh,Vl} ([64][88] bf16 = 11264 each; buf 45056)
// total 180224 B dynamic smem, 1 CTA/SM, 16 warps/SM.
// ---------------------------------------------------------------------------
#define AT_SMEM_BYTES 180224

__global__ __launch_bounds__(512)
void attn_kernel(float* __restrict__ loss_out)
{
    __nv_bfloat16* smbf = (__nv_bfloat16*)dynsm;

    const uint32_t smu   = (uint32_t)__cvta_generic_to_shared(smbf);
    const uint32_t kvb32 = smu + 90112u;

    const int tid  = threadIdx.x;
    const int warp = tid >> 5, lane = tid & 31;
    const int gr = lane >> 2, c4 = lane & 3;

    const int bh = blockIdx.y, b = bh >> 4, h = bh & 15;
    const int n0 = blockIdx.x * 256;

    // ldmatrix per-lane address components
    const int a_row = (lane & 15);
    const int a_kc  = (lane >> 4) * 8;
    const int b_row = (lane & 7) + ((lane >> 4) & 1) * 8;
    const int b_kc  = ((lane >> 3) & 1) * 8;

    auto prefetch = [&](int t, int buf) {
        const int kt = t & 15;
        const __nv_bfloat16* s0 = (t < 16) ? g_kh : g_ekh;
        const __nv_bfloat16* s1 = (t < 16) ? g_kl : g_ekl;
        const __nv_bfloat16* s2 = (t < 16) ? g_vh : g_evh;
        const __nv_bfloat16* s3 = (t < 16) ? g_vl : g_evl;
        const size_t toff = (((size_t)bh << 10) + kt * 64) * HDIM;
#pragma unroll
        for (int r = 0; r < 5; r++) {
            int e = tid + r * 512;
            if (e < 2304) {
                int arr = e / 576, rem = e - arr * 576;
                int row = rem / 9,  ch  = rem - row * 9;
                const __nv_bfloat16* src =
                    (arr == 0 ? s0 : arr == 1 ? s1 : arr == 2 ? s2 : s3)
                    + toff + row * HDIM + ch * 8;
                cp16(kvb32 + buf * 45056u + arr * 11264u
                           + (uint32_t)(row * 176 + ch * 16), src);
            }
        }
        asm volatile("cp.async.commit_group;");
    };
    prefetch(0, 0);

    // zero pads (cols 72..87): Q arrays (2 x 256 rows) + KV arrays (8 x 64 rows)
    for (int i = tid; i < 4096; i += 512) {
        int arr = i >> 11, rem = i & 2047;
        int row = rem >> 3, cp = rem & 7;
        *(uint32_t*)(smbf + arr * 22528 + row * 88 + 72 + 2 * cp) = 0;
    }
    for (int i = tid; i < 4096; i += 512) {
        int arr = i >> 9, rem = i & 511;
        int row = rem >> 3, cp = rem & 7;
        *(uint32_t*)(smbf + 45056 + arr * 5632 + row * 88 + 72 + 2 * cp) = 0;
    }

    // load Q tile: 256 rows x 36 chunks
    {
        const uint32_t* qh = (const uint32_t*)g_qh;
        const uint32_t* ql = (const uint32_t*)g_ql;
        const size_t qoff = (((size_t)bh << 10) + n0) * 36;
#pragma unroll
        for (int r = 0; r < 18; r++) {
            int e = tid + r * 512;                    // 0..9215
            int row = e / 36, ch = e - row * 36;
            size_t gi = qoff + row * 36 + ch;
            *(uint32_t*)(smbf + row * 88 + ch * 2) = qh[gi];
            *(uint32_t*)(smbf + 22528 + row * 88 + ch * 2) = ql[gi];
        }
    }

    float lsum = 0.f;
    float m0 = -1e30f, m1 = -1e30f, l0 = 0.f, l1 = 0.f;
    float oacc[9][4];
#pragma unroll
    for (int j = 0; j < 9; j++)
#pragma unroll
        for (int r = 0; r < 4; r++) oacc[j][r] = 0.f;

    const int qrow = warp * 16 + gr;

#pragma unroll 1
    for (int t = 0; t < 32; t++) {
        const int buf = t & 1;

        asm volatile("cp.async.wait_group 0;");
        __syncthreads();
        if (t + 1 < 32) prefetch(t + 1, buf ^ 1);

        const uint32_t kh_base = kvb32 + buf * 45056u;
        const uint32_t vh_base = kh_base + 22528u;

        // ---- scores ----
        float sacc[8][4];
#pragma unroll
        for (int j = 0; j < 8; j++)
#pragma unroll
            for (int r = 0; r < 4; r++) sacc[j][r] = 0.f;

#pragma unroll
        for (int ks = 0; ks < 5; ks++) {
            const uint32_t qa = smu +
                (uint32_t)((warp * 16 + a_row) * 176 + (ks * 16 + a_kc) * 2);
            uint32_t ah[4], al[4];
            ldsm_x4(ah[0], ah[1], ah[2], ah[3], qa);
            ldsm_x4(al[0], al[1], al[2], al[3], qa + 45056u);
#pragma unroll
            for (int jp = 0; jp < 4; jp++) {
                const uint32_t ka = kh_base +
                    (uint32_t)((jp * 16 + b_row) * 176 + (ks * 16 + b_kc) * 2);
                uint32_t kh4[4], kl4[4];
                ldsm_x4(kh4[0], kh4[1], kh4[2], kh4[3], ka);
                ldsm_x4(kl4[0], kl4[1], kl4[2], kl4[3], ka + 11264u);
                mma_bf16(sacc[2*jp],     ah, kh4);
                mma_bf16(sacc[2*jp],     ah, kl4);
                mma_bf16(sacc[2*jp],     al, kh4);
                mma_bf16(sacc[2*jp + 1], ah, kh4 + 2);
                mma_bf16(sacc[2*jp + 1], ah, kl4 + 2);
                mma_bf16(sacc[2*jp + 1], al, kh4 + 2);
            }
        }

        // ---- online softmax in registers ----
        {
            float t0 = -1e30f, t1 = -1e30f;
#pragma unroll
            for (int j = 0; j < 8; j++) {
                t0 = fmaxf(t0, fmaxf(sacc[j][0], sacc[j][1]));
                t1 = fmaxf(t1, fmaxf(sacc[j][2], sacc[j][3]));
            }
            t0 = fmaxf(t0, __shfl_xor_sync(0xffffffffu, t0, 1));
            t0 = fmaxf(t0, __shfl_xor_sync(0xffffffffu, t0, 2));
            t1 = fmaxf(t1, __shfl_xor_sync(0xffffffffu, t1, 1));
            t1 = fmaxf(t1, __shfl_xor_sync(0xffffffffu, t1, 2));
            const float nm0 = fmaxf(m0, t0), nm1 = fmaxf(m1, t1);
            const float cr0 = __expf(m0 - nm0), cr1 = __expf(m1 - nm1);
            float s0 = 0.f, s1 = 0.f;
#pragma unroll
            for (int j = 0; j < 8; j++) {
                sacc[j][0] = __expf(sacc[j][0] - nm0);
                sacc[j][1] = __expf(sacc[j][1] - nm0);
                sacc[j][2] = __expf(sacc[j][2] - nm1);
                sacc[j][3] = __expf(sacc[j][3] - nm1);
                s0 += sacc[j][0] + sacc[j][1];
                s1 += sacc[j][2] + sacc[j][3];
            }
            s0 += __shfl_xor_sync(0xffffffffu, s0, 1);
            s0 += __shfl_xor_sync(0xffffffffu, s0, 2);
            s1 += __shfl_xor_sync(0xffffffffu, s1, 1);
            s1 += __shfl_xor_sync(0xffffffffu, s1, 2);
            l0 = l0 * cr0 + s0; l1 = l1 * cr1 + s1;
            m0 = nm0; m1 = nm1;
#pragma unroll
            for (int j = 0; j < 9; j++) {
                oacc[j][0] *= cr0; oacc[j][1] *= cr0;
                oacc[j][2] *= cr1; oacc[j][3] *= cr1;
            }
        }

        // ---- PV: register P fragments; V via ldmatrix.x4.trans ----
#pragma unroll
        for (int ks = 0; ks < 4; ks++) {
            uint32_t ph[4], pl[4];
            split2(sacc[2*ks][0],   sacc[2*ks][1],   ph[0], pl[0]);
            split2(sacc[2*ks][2],   sacc[2*ks][3],   ph[1], pl[1]);
            split2(sacc[2*ks+1][0], sacc[2*ks+1][1], ph[2], pl[2]);
            split2(sacc[2*ks+1][2], sacc[2*ks+1][3], ph[3], pl[3]);
            const uint32_t va_base = vh_base +
                (uint32_t)(((ks * 16 + (lane & 15)) * 88) * 2) +
                (uint32_t)((lane >> 4) * 16);
#pragma unroll
            for (int jp = 0; jp < 8; jp += 2) {
                const uint32_t va = va_base + (uint32_t)(jp * 16);
                uint32_t vh4[4], vl4[4];
                ldsm_x4_trans(vh4[0], vh4[1], vh4[2], vh4[3], va);
                ldsm_x4_trans(vl4[0], vl4[1], vl4[2], vl4[3], va + 11264u);
                mma_bf16(oacc[jp],     ph, vh4);
                mma_bf16(oacc[jp],     ph, vl4);
                mma_bf16(oacc[jp],     pl, vh4);
                mma_bf16(oacc[jp + 1], ph, vh4 + 2);
                mma_bf16(oacc[jp + 1], ph, vl4 + 2);
                mma_bf16(oacc[jp + 1], pl, vh4 + 2);
            }
            {   // j = 8 remainder
                const uint32_t va = vh_base +
                    (uint32_t)(((ks * 16 + (lane & 15)) * 88) * 2) +
                    (uint32_t)(8 * 16);
                uint32_t vh2[2], vl2[2];
                ldsm_x2_trans(vh2[0], vh2[1], va);
                ldsm_x2_trans(vl2[0], vl2[1], va + 11264u);
                mma_bf16(oacc[8], ph, vh2);
                mma_bf16(oacc[8], ph, vl2);
                mma_bf16(oacc[8], pl, vh2);
            }
        }

        // ---- pass epilogues ----
        if (t == 15) {
            const float i0 = 1.0f / l0, i1 = 1.0f / l1;
            const int q0 = n0 + qrow;
            uint32_t* dh = (uint32_t*)g_oh;
            uint32_t* dl = (uint32_t*)g_ol;
#pragma unroll
            for (int j = 0; j < 9; j++) {
                const int dim = j * 8 + 2 * c4;
                const size_t i0x = (((size_t)(b * SEQ + q0)) * DIM
                                    + h * HDIM + dim) >> 1;
                const size_t i1x = (((size_t)(b * SEQ + q0 + 8)) * DIM
                                    + h * HDIM + dim) >> 1;
                uint32_t hh, ll;
                split2(oacc[j][0] * i0, oacc[j][1] * i0, hh, ll);
                dh[i0x] = hh; dl[i0x] = ll;
                split2(oacc[j][2] * i1, oacc[j][3] * i1, hh, ll);
                dh[i1x] = hh; dl[i1x] = ll;
            }
            m0 = -1e30f; m1 = -1e30f; l0 = 0.f; l1 = 0.f;
#pragma unroll
            for (int j = 0; j < 9; j++)
#pragma unroll
                for (int r = 0; r < 4; r++) oacc[j][r] = 0.f;
        } else if (t == 31) {
            const float i0 = 1.0f / l0, i1 = 1.0f / l1;
            const int q0 = n0 + qrow;
            const uint32_t* dh = (const uint32_t*)g_oh;
            const uint32_t* dl = (const uint32_t*)g_ol;
#pragma unroll
            for (int j = 0; j < 9; j++) {
                const int dim = j * 8 + 2 * c4;
                const size_t i0x = (((size_t)(b * SEQ + q0)) * DIM
                                    + h * HDIM + dim) >> 1;
                const size_t i1x = (((size_t)(b * SEQ + q0 + 8)) * DIM
                                    + h * HDIM + dim) >> 1;
                float2 x0 = unsplit(dh[i0x], dl[i0x]);
                float2 x1 = unsplit(dh[i1x], dl[i1x]);
                float e0 = x0.x - oacc[j][0] * i0;
                float e1 = x0.y - oacc[j][1] * i0;
                float e2 = x1.x - oacc[j][2] * i1;
                float e3 = x1.y - oacc[j][3] * i1;
                lsum += e0*e0 + e1*e1 + e2*e2 + e3*e3;
            }
        }
    }

    lsum *= (1.0f / TOTAL_ELEMS);
#pragma unroll
    for (int o = 16; o > 0; o >>= 1)
        lsum += __shfl_down_sync(0xffffffffu, lsum, o);
    if (lane == 0) atomicAdd(loss_out, lsum);
}

// ---------------------------------------------------------------------------
extern "C" void kernel_launch(void* const* d_in, const int* in_sizes, int n_in,
                              void* d_out, int out_size)
{
    const float* x      = (const float*)d_in[0];
    const float* enc_k  = (const float*)d_in[1];
    const float* enc_v  = (const float*)d_in[2];
    const float* qkv_w  = (const float*)d_in[3];
    const float* qkv_b  = (const float*)d_in[4];
    const float* proj_w = (const float*)d_in[5];
    const float* proj_b = (const float*)d_in[6];
    float* out = (float*)d_out;
    float* loss_ptr = out + (out_size - 1);

    __nv_bfloat16 *xh, *xl, *wqh, *wql, *wph, *wpl, *oh, *ol;
    cudaGetSymbolAddress((void**)&xh,  g_xh);   cudaGetSymbolAddress((void**)&xl,  g_xl);
    cudaGetSymbolAddress((void**)&wqh, g_wqh);  cudaGetSymbolAddress((void**)&wql, g_wql);
    cudaGetSymbolAddress((void**)&wph, g_wph);  cudaGetSymbolAddress((void**)&wpl, g_wpl);
    cudaGetSymbolAddress((void**)&oh,  g_oh);   cudaGetSymbolAddress((void**)&ol,  g_ol);

    static bool attr_set = false;
    if (!attr_set) {
        cudaFuncSetAttribute(attn_kernel,
                             cudaFuncAttributeMaxDynamicSharedMemorySize, AT_SMEM_BYTES);
        cudaFuncSetAttribute(gemm_mma_kernel<0>,
                             cudaFuncAttributeMaxDynamicSharedMemorySize, GM_SMEM_BYTES);
        cudaFuncSetAttribute(gemm_mma_kernel<1>,
                             cudaFuncAttributeMaxDynamicSharedMemorySize, GM_SMEM_BYTES);
        attr_set = true;
    }

    cudaMemsetAsync(loss_ptr, 0, sizeof(float));

    // 0) fused fp32 -> bf16 hi/lo splits (all 5 tensors, one launch)
    split_all_kernel<<<(N4_ALL + 255) / 256, 256>>>(x, qkv_w, proj_w, enc_k, enc_v);

    // 1) QKV GEMM (tensor cores) -> head-major bf16 hi/lo Q(scaled)/K/V
    gemm_mma_kernel<1><<<dim3(QKVN / 128, ROWS / 128), 256, GM_SMEM_BYTES>>>(
        xh, xl, wqh, wql, qkv_b, nullptr, ROWS, QKVN, DIM);

    // 2) Dual attention + loss (256q tiles, 512 threads) -> g_oh/g_ol
    attn_kernel<<<dim3(SEQ / 256, BATCH * HEADS), 512, AT_SMEM_BYTES>>>(loss_ptr);

    // 3) proj GEMM (tensor cores) -> out
    gemm_mma_kernel<0><<<dim3(DIM / 128, ROWS / 128), 256, GM_SMEM_BYTES>>>(
        oh, ol, wph, wpl, proj_b, out, ROWS, DIM, DIM);
}

// round 16
// speedup vs baseline: 1.3215x; 1.0018x over previous
#include <cuda_runtime.h>
#include <cuda_bf16.h>
#include <cstdint>
#include <cstddef>

// Problem constants (fixed by setup_inputs)
#define BATCH 4
#define SEQ   1024
#define DIM   1152
#define HEADS 16
#define HDIM  72
#define ROWS  (BATCH*SEQ)          // 4096
#define QKVN  (3*DIM)              // 3456
#define TOTAL_ELEMS 4718592.0f     // B*H*N*hd for loss mean
#define QSCALE 0.11785113f         // 72^-0.5

// Scratch (static device allocation — allowed). All bf16 hi/lo pairs.
__device__ __align__(16) __nv_bfloat16 g_xh [(size_t)ROWS * DIM];
__device__ __align__(16) __nv_bfloat16 g_xl [(size_t)ROWS * DIM];
__device__ __align__(16) __nv_bfloat16 g_wqh[(size_t)QKVN * DIM];
__device__ __align__(16) __nv_bfloat16 g_wql[(size_t)QKVN * DIM];
__device__ __align__(16) __nv_bfloat16 g_wph[(size_t)DIM * DIM];
__device__ __align__(16) __nv_bfloat16 g_wpl[(size_t)DIM * DIM];
// head-major [bh][seq][72] bf16 Q/K/V (hi/lo), written by QKV GEMM epilogue
__device__ __align__(16) __nv_bfloat16 g_qh [(size_t)ROWS * DIM];
__device__ __align__(16) __nv_bfloat16 g_ql [(size_t)ROWS * DIM];
__device__ __align__(16) __nv_bfloat16 g_kh [(size_t)ROWS * DIM];
__device__ __align__(16) __nv_bfloat16 g_kl [(size_t)ROWS * DIM];
__device__ __align__(16) __nv_bfloat16 g_vh [(size_t)ROWS * DIM];
__device__ __align__(16) __nv_bfloat16 g_vl [(size_t)ROWS * DIM];
// encoder K/V pre-split (same [bh][seq][72] layout as the fp32 inputs)
__device__ __align__(16) __nv_bfloat16 g_ekh[(size_t)ROWS * DIM];
__device__ __align__(16) __nv_bfloat16 g_ekl[(size_t)ROWS * DIM];
__device__ __align__(16) __nv_bfloat16 g_evh[(size_t)ROWS * DIM];
__device__ __align__(16) __nv_bfloat16 g_evl[(size_t)ROWS * DIM];
// attention output (hi/lo) -> proj GEMM input
__device__ __align__(16) __nv_bfloat16 g_oh [(size_t)ROWS * DIM];
__device__ __align__(16) __nv_bfloat16 g_ol [(size_t)ROWS * DIM];

extern __shared__ char dynsm[];

// ---------------------------------------------------------------------------
// helpers
// ---------------------------------------------------------------------------
__device__ __forceinline__ void cp16(uint32_t dst, const void* src) {
    asm volatile("cp.async.cg.shared.global [%0], [%1], 16;" :: "r"(dst), "l"(src));
}
__device__ __forceinline__ void mma_bf16(float* d, const uint32_t* a, const uint32_t* b) {
    asm volatile(
        "mma.sync.aligned.m16n8k16.row.col.f32.bf16.bf16.f32 "
        "{%0,%1,%2,%3}, {%4,%5,%6,%7}, {%8,%9}, {%0,%1,%2,%3};"
        : "+f"(d[0]), "+f"(d[1]), "+f"(d[2]), "+f"(d[3])
        : "r"(a[0]), "r"(a[1]), "r"(a[2]), "r"(a[3]), "r"(b[0]), "r"(b[1]));
}
__device__ __forceinline__ void ldsm_x2_trans(uint32_t& r0, uint32_t& r1, uint32_t saddr) {
    asm volatile("ldmatrix.sync.aligned.m8n8.x2.trans.shared.b16 {%0,%1}, [%2];"
                 : "=r"(r0), "=r"(r1) : "r"(saddr));
}
__device__ __forceinline__ void ldsm_x4_trans(uint32_t& r0, uint32_t& r1,
                                              uint32_t& r2, uint32_t& r3, uint32_t saddr) {
    asm volatile("ldmatrix.sync.aligned.m8n8.x4.trans.shared.b16 {%0,%1,%2,%3}, [%4];"
                 : "=r"(r0), "=r"(r1), "=r"(r2), "=r"(r3) : "r"(saddr));
}
__device__ __forceinline__ void ldsm_x4(uint32_t& r0, uint32_t& r1,
                                        uint32_t& r2, uint32_t& r3, uint32_t saddr) {
    asm volatile("ldmatrix.sync.aligned.m8n8.x4.shared.b16 {%0,%1,%2,%3}, [%4];"
                 : "=r"(r0), "=r"(r1), "=r"(r2), "=r"(r3) : "r"(saddr));
}
__device__ __forceinline__ void split2(float x, float y, uint32_t& h, uint32_t& l) {
    __nv_bfloat16 h0 = __float2bfloat16(x);
    __nv_bfloat16 h1 = __float2bfloat16(y);
    __nv_bfloat16 l0 = __float2bfloat16(x - __bfloat162float(h0));
    __nv_bfloat16 l1 = __float2bfloat16(y - __bfloat162float(h1));
    __nv_bfloat162 hh; hh.x = h0; hh.y = h1;
    __nv_bfloat162 ll; ll.x = l0; ll.y = l1;
    h = *(uint32_t*)&hh;
    l = *(uint32_t*)&ll;
}
__device__ __forceinline__ float2 unsplit(uint32_t h, uint32_t l) {
    __nv_bfloat162 hh = *(__nv_bfloat162*)&h;
    __nv_bfloat162 ll = *(__nv_bfloat162*)&l;
    return make_float2(__bfloat162float(hh.x) + __bfloat162float(ll.x),
                       __bfloat162float(hh.y) + __bfloat162float(ll.y));
}

// ---------------------------------------------------------------------------
// Fused fp32 -> bf16 (hi, lo) split over all 5 input tensors (one launch).
// ---------------------------------------------------------------------------
#define N4_X  ((ROWS * DIM) / 4)
#define N4_WQ ((QKVN * DIM) / 4)
#define N4_WP ((DIM * DIM) / 4)
#define N4_ALL (N4_X + N4_WQ + N4_WP + N4_X + N4_X)

__global__ __launch_bounds__(256)
void split_all_kernel(const float* __restrict__ x,    const float* __restrict__ wq,
                      const float* __restrict__ wp,   const float* __restrict__ ek,
                      const float* __restrict__ ev)
{
    int i = blockIdx.x * 256 + threadIdx.x;
    if (i >= N4_ALL) return;
    const float* src;
    __nv_bfloat16 *hi, *lo;
    int o = i;
    if (o < N4_X)                   { src = x;  hi = g_xh;  lo = g_xl;  }
    else if ((o -= N4_X) < N4_WQ)   { src = wq; hi = g_wqh; lo = g_wql; }
    else if ((o -= N4_WQ) < N4_WP)  { src = wp; hi = g_wph; lo = g_wpl; }
    else if ((o -= N4_WP) < N4_X)   { src = ek; hi = g_ekh; lo = g_ekl; }
    else                            { o -= N4_X; src = ev; hi = g_evh; lo = g_evl; }

    float4 v = ((const float4*)src)[o];
    uint32_t h0, l0, h1, l1;
    split2(v.x, v.y, h0, l0);
    split2(v.z, v.w, h1, l1);
    ((uint32_t*)hi)[2 * o]     = h0;
    ((uint32_t*)hi)[2 * o + 1] = h1;
    ((uint32_t*)lo)[2 * o]     = l0;
    ((uint32_t*)lo)[2 * o + 1] = l1;
}

// ---------------------------------------------------------------------------
// Tensor-core GEMM (3-term bf16 split), ldmatrix.x4 fragment loads,
// term-major MMA ordering (accumulator RAW distance 4).
// EPI=0: fp32 C (+bias). EPI=1: QKV epilogue (head-major bf16 hi/lo).
// ---------------------------------------------------------------------------
#define GM_SMEM_BYTES 81920

template<int EPI>
__global__ __launch_bounds__(256, 2)
void gemm_mma_kernel(const __nv_bfloat16* __restrict__ Ah, const __nv_bfloat16* __restrict__ Al,
                     const __nv_bfloat16* __restrict__ Bh, const __nv_bfloat16* __restrict__ Bl,
                     const float* __restrict__ bias, float* __restrict__ C,
                     int M, int N, int K)
{
    const uint32_t sb32 = (uint32_t)__cvta_generic_to_shared(dynsm);

    const int tid  = threadIdx.x;
    const int warp = tid >> 5, lane = tid & 31;
    const int wm = warp >> 2, wn = warp & 3;
    const int gr = lane >> 2, c4 = lane & 3;
    const int m0 = blockIdx.y * 128, n0 = blockIdx.x * 128;

    const int l_row0 = tid >> 2,            l_cb0 = (tid & 3) << 3;
    const int l_row1 = (tid + 256) >> 2,    l_cb1 = ((tid + 256) & 3) << 3;

    const int a_row = (lane & 15);
    const int a_kc  = (lane >> 4) * 8;
    const int b_row = (lane & 7) + ((lane >> 4) & 1) * 8;
    const int b_kc  = ((lane >> 3) & 1) * 8;

    float acc[4][4][4];
#pragma unroll
    for (int i = 0; i < 4; i++)
#pragma unroll
        for (int j = 0; j < 4; j++)
#pragma unroll
            for (int r = 0; r < 4; r++) acc[i][j][r] = 0.f;

    const int nkt = K >> 5;

    auto load_tile = [&](int stage, int kt) {
        const int k0 = kt << 5;
        const uint32_t st = sb32 + stage * 40960u;
        cp16(st + (uint32_t)(l_row0 * 80 + l_cb0 * 2),
             Ah + (size_t)(m0 + l_row0) * K + k0 + l_cb0);
        cp16(st + (uint32_t)(l_row1 * 80 + l_cb1 * 2),
             Ah + (size_t)(m0 + l_row1) * K + k0 + l_cb1);
        cp16(st + 10240u + (uint32_t)(l_row0 * 80 + l_cb0 * 2),
             Al + (size_t)(m0 + l_row0) * K + k0 + l_cb0);
        cp16(st + 10240u + (uint32_t)(l_row1 * 80 + l_cb1 * 2),
             Al + (size_t)(m0 + l_row1) * K + k0 + l_cb1);
        cp16(st + 20480u + (uint32_t)(l_row0 * 80 + l_cb0 * 2),
             Bh + (size_t)(n0 + l_row0) * K + k0 + l_cb0);
        cp16(st + 20480u + (uint32_t)(l_row1 * 80 + l_cb1 * 2),
             Bh + (size_t)(n0 + l_row1) * K + k0 + l_cb1);
        cp16(st + 30720u + (uint32_t)(l_row0 * 80 + l_cb0 * 2),
             Bl + (size_t)(n0 + l_row0) * K + k0 + l_cb0);
        cp16(st + 30720u + (uint32_t)(l_row1 * 80 + l_cb1 * 2),
             Bl + (size_t)(n0 + l_row1) * K + k0 + l_cb1);
        asm volatile("cp.async.commit_group;");
    };

    load_tile(0, 0);
    load_tile(1, 1);

    for (int kt = 0; kt < nkt; kt++) {
        if (kt + 1 < nkt) asm volatile("cp.async.wait_group 1;");
        else              asm volatile("cp.async.wait_group 0;");
        __syncthreads();

        const uint32_t st = sb32 + (kt & 1) * 40960u;

#pragma unroll
        for (int ks = 0; ks < 2; ks++) {
            uint32_t bh[4][2], bl[4][2];
#pragma unroll
            for (int jp = 0; jp < 2; jp++) {
                const uint32_t ba = st + 20480u +
                    (uint32_t)((wn * 32 + jp * 16 + b_row) * 80 +
                               (ks * 16 + b_kc) * 2);
                ldsm_x4(bh[2*jp][0], bh[2*jp][1], bh[2*jp+1][0], bh[2*jp+1][1], ba);
                ldsm_x4(bl[2*jp][0], bl[2*jp][1], bl[2*jp+1][0], bl[2*jp+1][1], ba + 10240u);
            }
#pragma unroll
            for (int i = 0; i < 4; i++) {
                const uint32_t aa = st +
                    (uint32_t)((wm * 64 + i * 16 + a_row) * 80 +
                               (ks * 16 + a_kc) * 2);
                uint32_t ah[4], al[4];
                ldsm_x4(ah[0], ah[1], ah[2], ah[3], aa);
                ldsm_x4(al[0], al[1], al[2], al[3], aa + 10240u);
                // term-major: accumulator RAW distance = 4
#pragma unroll
                for (int j = 0; j < 4; j++) mma_bf16(acc[i][j], ah, bh[j]);
#pragma unroll
                for (int j = 0; j < 4; j++) mma_bf16(acc[i][j], ah, bl[j]);
#pragma unroll
                for (int j = 0; j < 4; j++) mma_bf16(acc[i][j], al, bh[j]);
            }
        }
        __syncthreads();
        if (kt + 2 < nkt) load_tile(kt & 1, kt + 2);
    }

#pragma unroll
    for (int j = 0; j < 4; j++) {
        const int gn = n0 + wn * 32 + j * 8 + 2 * c4;
        const float b0 = bias[gn], b1 = bias[gn + 1];
        if (EPI == 0) {
#pragma unroll
            for (int i = 0; i < 4; i++) {
                const int gm = m0 + wm * 64 + i * 16 + gr;
                float2 w0, w1;
                w0.x = acc[i][j][0] + b0; w0.y = acc[i][j][1] + b1;
                w1.x = acc[i][j][2] + b0; w1.y = acc[i][j][3] + b1;
                *(float2*)&C[(size_t)gm * N + gn] = w0;
                *(float2*)&C[(size_t)(gm + 8) * N + gn] = w1;
            }
        } else {
            const int part = gn / DIM;
            const int rem  = gn - part * DIM;
            const int hh   = rem / HDIM;
            const int dd   = rem - hh * HDIM;          // even
            uint32_t* dsth;
            uint32_t* dstl;
            float sc = 1.f;
            if (part == 0)      { dsth = (uint32_t*)g_qh; dstl = (uint32_t*)g_ql; sc = QSCALE; }
            else if (part == 1) { dsth = (uint32_t*)g_kh; dstl = (uint32_t*)g_kl; }
            else                { dsth = (uint32_t*)g_vh; dstl = (uint32_t*)g_vl; }
#pragma unroll
            for (int i = 0; i < 4; i++) {
                const int gm = m0 + wm * 64 + i * 16 + gr;
                const int b_ = gm >> 10, seq = gm & 1023;
                const size_t idx = (((size_t)(b_ * HEADS + hh) << 10) + seq) * 36 + (dd >> 1);
                uint32_t h_, l_;
                split2((acc[i][j][0] + b0) * sc, (acc[i][j][1] + b1) * sc, h_, l_);
                dsth[idx] = h_; dstl[idx] = l_;
                split2((acc[i][j][2] + b0) * sc, (acc[i][j][3] + b1) * sc, h_, l_);
                dsth[idx + 8 * 36] = h_; dstl[idx + 8 * 36] = l_;
            }
        }
    }
}

// ---------------------------------------------------------------------------
// Attention v10: 256-query tile, 512 threads (16 warps, 16 q-rows each),
// FA2 register P, ldmatrix.x4 fragments, term-major MMA ordering.
// smem: sQh @0, sQl @45056 (each [256][88]); KV @90112: 2 bufs x {Kh,Kl,Vh,Vl}
// ([64][88], 11264 B each). Total 180224 B, 1 CTA/SM, 16 warps.
// ---------------------------------------------------------------------------
#define AT_SMEM_BYTES 180224

__global__ __launch_bounds__(512)
void attn_kernel(float* __restrict__ loss_out)
{
    __nv_bfloat16* smbf = (__nv_bfloat16*)dynsm;

    const uint32_t smu   = (uint32_t)__cvta_generic_to_shared(smbf);
    const uint32_t kvb32 = smu + 90112u;

    const int tid  = threadIdx.x;
    const int warp = tid >> 5, lane = tid & 31;
    const int gr = lane >> 2, c4 = lane & 3;

    const int bh = blockIdx.y, b = bh >> 4, h = bh & 15;
    const int n0 = blockIdx.x * 256;

    const int a_row = (lane & 15);
    const int a_kc  = (lane >> 4) * 8;
    const int b_row = (lane & 7) + ((lane >> 4) & 1) * 8;
    const int b_kc  = ((lane >> 3) & 1) * 8;

    auto prefetch = [&](int t, int buf) {
        const int kt = t & 15;
        const __nv_bfloat16* s0 = (t < 16) ? g_kh : g_ekh;
        const __nv_bfloat16* s1 = (t < 16) ? g_kl : g_ekl;
        const __nv_bfloat16* s2 = (t < 16) ? g_vh : g_evh;
        const __nv_bfloat16* s3 = (t < 16) ? g_vl : g_evl;
        const size_t toff = (((size_t)bh << 10) + kt * 64) * HDIM;
#pragma unroll
        for (int r = 0; r < 5; r++) {
            int e = tid + r * 512;
            if (e < 2304) {
                int arr = e / 576, rem = e - arr * 576;
                int row = rem / 9,  ch  = rem - row * 9;
                const __nv_bfloat16* src =
                    (arr == 0 ? s0 : arr == 1 ? s1 : arr == 2 ? s2 : s3)
                    + toff + row * HDIM + ch * 8;
                cp16(kvb32 + buf * 45056u + arr * 11264u
                           + (uint32_t)(row * 176 + ch * 16), src);
            }
        }
        asm volatile("cp.async.commit_group;");
    };
    prefetch(0, 0);

    // zero pads (cols 72..87)
    for (int i = tid; i < 4096; i += 512) {
        int arr = i >> 11, rem = i & 2047;
        int row = rem >> 3, cp = rem & 7;
        *(uint32_t*)(smbf + arr * 22528 + row * 88 + 72 + 2 * cp) = 0;
    }
    for (int i = tid; i < 4096; i += 512) {
        int arr = i >> 9, rem = i & 511;
        int row = rem >> 3, cp = rem & 7;
        *(uint32_t*)(smbf + 45056 + arr * 5632 + row * 88 + 72 + 2 * cp) = 0;
    }

    // load Q tile: 256 rows x 36 chunks
    {
        const uint32_t* qh = (const uint32_t*)g_qh;
        const uint32_t* ql = (const uint32_t*)g_ql;
        const size_t qoff = (((size_t)bh << 10) + n0) * 36;
#pragma unroll
        for (int r = 0; r < 18; r++) {
            int e = tid + r * 512;
            int row = e / 36, ch = e - row * 36;
            size_t gi = qoff + row * 36 + ch;
            *(uint32_t*)(smbf + row * 88 + ch * 2) = qh[gi];
            *(uint32_t*)(smbf + 22528 + row * 88 + ch * 2) = ql[gi];
        }
    }

    float lsum = 0.f;
    float m0 = -1e30f, m1 = -1e30f, l0 = 0.f, l1 = 0.f;
    float oacc[9][4];
#pragma unroll
    for (int j = 0; j < 9; j++)
#pragma unroll
        for (int r = 0; r < 4; r++) oacc[j][r] = 0.f;

    const int qrow = warp * 16 + gr;

#pragma unroll 1
    for (int t = 0; t < 32; t++) {
        const int buf = t & 1;

        asm volatile("cp.async.wait_group 0;");
        __syncthreads();
        if (t + 1 < 32) prefetch(t + 1, buf ^ 1);

        const uint32_t kh_base = kvb32 + buf * 45056u;
        const uint32_t vh_base = kh_base + 22528u;

        // ---- scores: term-major across jp pairs (RAW distance 4) ----
        float sacc[8][4];
#pragma unroll
        for (int j = 0; j < 8; j++)
#pragma unroll
            for (int r = 0; r < 4; r++) sacc[j][r] = 0.f;

#pragma unroll
        for (int ks = 0; ks < 5; ks++) {
            const uint32_t qa = smu +
                (uint32_t)((warp * 16 + a_row) * 176 + (ks * 16 + a_kc) * 2);
            uint32_t ah[4], al[4];
            ldsm_x4(ah[0], ah[1], ah[2], ah[3], qa);
            ldsm_x4(al[0], al[1], al[2], al[3], qa + 45056u);
#pragma unroll
            for (int jpp = 0; jpp < 4; jpp += 2) {
                const uint32_t kaA = kh_base +
                    (uint32_t)((jpp * 16 + b_row) * 176 + (ks * 16 + b_kc) * 2);
                const uint32_t kaB = kh_base +
                    (uint32_t)(((jpp + 1) * 16 + b_row) * 176 + (ks * 16 + b_kc) * 2);
                uint32_t khA[4], klA[4], khB[4], klB[4];
                ldsm_x4(khA[0], khA[1], khA[2], khA[3], kaA);
                ldsm_x4(klA[0], klA[1], klA[2], klA[3], kaA + 11264u);
                ldsm_x4(khB[0], khB[1], khB[2], khB[3], kaB);
                ldsm_x4(klB[0], klB[1], klB[2], klB[3], kaB + 11264u);
                float* s0p = sacc[2*jpp];
                float* s1p = sacc[2*jpp + 1];
                float* s2p = sacc[2*jpp + 2];
                float* s3p = sacc[2*jpp + 3];
                mma_bf16(s0p, ah, khA);     mma_bf16(s1p, ah, khA + 2);
                mma_bf16(s2p, ah, khB);     mma_bf16(s3p, ah, khB + 2);
                mma_bf16(s0p, ah, klA);     mma_bf16(s1p, ah, klA + 2);
                mma_bf16(s2p, ah, klB);     mma_bf16(s3p, ah, klB + 2);
                mma_bf16(s0p, al, khA);     mma_bf16(s1p, al, khA + 2);
                mma_bf16(s2p, al, khB);     mma_bf16(s3p, al, khB + 2);
            }
        }

        // ---- online softmax in registers ----
        {
            float t0 = -1e30f, t1 = -1e30f;
#pragma unroll
            for (int j = 0; j < 8; j++) {
                t0 = fmaxf(t0, fmaxf(sacc[j][0], sacc[j][1]));
                t1 = fmaxf(t1, fmaxf(sacc[j][2], sacc[j][3]));
            }
            t0 = fmaxf(t0, __shfl_xor_sync(0xffffffffu, t0, 1));
            t0 = fmaxf(t0, __shfl_xor_sync(0xffffffffu, t0, 2));
            t1 = fmaxf(t1, __shfl_xor_sync(0xffffffffu, t1, 1));
            t1 = fmaxf(t1, __shfl_xor_sync(0xffffffffu, t1, 2));
            const float nm0 = fmaxf(m0, t0), nm1 = fmaxf(m1, t1);
            const float cr0 = __expf(m0 - nm0), cr1 = __expf(m1 - nm1);
            float s0 = 0.f, s1 = 0.f;
#pragma unroll
            for (int j = 0; j < 8; j++) {
                sacc[j][0] = __expf(sacc[j][0] - nm0);
                sacc[j][1] = __expf(sacc[j][1] - nm0);
                sacc[j][2] = __expf(sacc[j][2] - nm1);
                sacc[j][3] = __expf(sacc[j][3] - nm1);
                s0 += sacc[j][0] + sacc[j][1];
                s1 += sacc[j][2] + sacc[j][3];
            }
            s0 += __shfl_xor_sync(0xffffffffu, s0, 1);
            s0 += __shfl_xor_sync(0xffffffffu, s0, 2);
            s1 += __shfl_xor_sync(0xffffffffu, s1, 1);
            s1 += __shfl_xor_sync(0xffffffffu, s1, 2);
            l0 = l0 * cr0 + s0; l1 = l1 * cr1 + s1;
            m0 = nm0; m1 = nm1;
#pragma unroll
            for (int j = 0; j < 9; j++) {
                oacc[j][0] *= cr0; oacc[j][1] *= cr0;
                oacc[j][2] *= cr1; oacc[j][3] *= cr1;
            }
        }

        // ---- PV: register P; V via ldmatrix.x4.trans; term-major ----
#pragma unroll
        for (int ks = 0; ks < 4; ks++) {
            uint32_t ph[4], pl[4];
            split2(sacc[2*ks][0],   sacc[2*ks][1],   ph[0], pl[0]);
            split2(sacc[2*ks][2],   sacc[2*ks][3],   ph[1], pl[1]);
            split2(sacc[2*ks+1][0], sacc[2*ks+1][1], ph[2], pl[2]);
            split2(sacc[2*ks+1][2], sacc[2*ks+1][3], ph[3], pl[3]);
            const uint32_t va_base = vh_base +
                (uint32_t)(((ks * 16 + (lane & 15)) * 88) * 2) +
                (uint32_t)((lane >> 4) * 16);
#pragma unroll
            for (int jq = 0; jq < 8; jq += 4) {
                const uint32_t vaA = va_base + (uint32_t)(jq * 16);
                const uint32_t vaB = va_base + (uint32_t)((jq + 2) * 16);
                uint32_t vhA[4], vlA[4], vhB[4], vlB[4];
                ldsm_x4_trans(vhA[0], vhA[1], vhA[2], vhA[3], vaA);
                ldsm_x4_trans(vlA[0], vlA[1], vlA[2], vlA[3], vaA + 11264u);
                ldsm_x4_trans(vhB[0], vhB[1], vhB[2], vhB[3], vaB);
                ldsm_x4_trans(vlB[0], vlB[1], vlB[2], vlB[3], vaB + 11264u);
                float* o0 = oacc[jq];
                float* o1 = oacc[jq + 1];
                float* o2 = oacc[jq + 2];
                float* o3 = oacc[jq + 3];
                mma_bf16(o0, ph, vhA);      mma_bf16(o1, ph, vhA + 2);
                mma_bf16(o2, ph, vhB);      mma_bf16(o3, ph, vhB + 2);
                mma_bf16(o0, ph, vlA);      mma_bf16(o1, ph, vlA + 2);
                mma_bf16(o2, ph, vlB);      mma_bf16(o3, ph, vlB + 2);
                mma_bf16(o0, pl, vhA);      mma_bf16(o1, pl, vhA + 2);
                mma_bf16(o2, pl, vhB);      mma_bf16(o3, pl, vhB + 2);
            }
            {   // j = 8 remainder
                const uint32_t va = vh_base +
                    (uint32_t)(((ks * 16 + (lane & 15)) * 88) * 2) +
                    (uint32_t)(8 * 16);
                uint32_t vh2[2], vl2[2];
                ldsm_x2_trans(vh2[0], vh2[1], va);
                ldsm_x2_trans(vl2[0], vl2[1], va + 11264u);
                mma_bf16(oacc[8], ph, vh2);
                mma_bf16(oacc[8], ph, vl2);
                mma_bf16(oacc[8], pl, vh2);
            }
        }

        // ---- pass epilogues ----
        if (t == 15) {
            const float i0 = 1.0f / l0, i1 = 1.0f / l1;
            const int q0 = n0 + qrow;
            uint32_t* dh = (uint32_t*)g_oh;
            uint32_t* dl = (uint32_t*)g_ol;
#pragma unroll
            for (int j = 0; j < 9; j++) {
                const int dim = j * 8 + 2 * c4;
                const size_t i0x = (((size_t)(b * SEQ + q0)) * DIM
                                    + h * HDIM + dim) >> 1;
                const size_t i1x = (((size_t)(b * SEQ + q0 + 8)) * DIM
                                    + h * HDIM + dim) >> 1;
                uint32_t hh, ll;
                split2(oacc[j][0] * i0, oacc[j][1] * i0, hh, ll);
                dh[i0x] = hh; dl[i0x] = ll;
                split2(oacc[j][2] * i1, oacc[j][3] * i1, hh, ll);
                dh[i1x] = hh; dl[i1x] = ll;
            }
            m0 = -1e30f; m1 = -1e30f; l0 = 0.f; l1 = 0.f;
#pragma unroll
            for (int j = 0; j < 9; j++)
#pragma unroll
                for (int r = 0; r < 4; r++) oacc[j][r] = 0.f;
        } else if (t == 31) {
            const float i0 = 1.0f / l0, i1 = 1.0f / l1;
            const int q0 = n0 + qrow;
            const uint32_t* dh = (const uint32_t*)g_oh;
            const uint32_t* dl = (const uint32_t*)g_ol;
#pragma unroll
            for (int j = 0; j < 9; j++) {
                const int dim = j * 8 + 2 * c4;
                const size_t i0x = (((size_t)(b * SEQ + q0)) * DIM
                                    + h * HDIM + dim) >> 1;
                const size_t i1x = (((size_t)(b * SEQ + q0 + 8)) * DIM
                                    + h * HDIM + dim) >> 1;
                float2 x0 = unsplit(dh[i0x], dl[i0x]);
                float2 x1 = unsplit(dh[i1x], dl[i1x]);
                float e0 = x0.x - oacc[j][0] * i0;
                float e1 = x0.y - oacc[j][1] * i0;
                float e2 = x1.x - oacc[j][2] * i1;
                float e3 = x1.y - oacc[j][3] * i1;
                lsum += e0*e0 + e1*e1 + e2*e2 + e3*e3;
            }
        }
    }

    lsum *= (1.0f / TOTAL_ELEMS);
#pragma unroll
    for (int o = 16; o > 0; o >>= 1)
        lsum += __shfl_down_sync(0xffffffffu, lsum, o);
    if (lane == 0) atomicAdd(loss_out, lsum);
}

// ---------------------------------------------------------------------------
extern "C" void kernel_launch(void* const* d_in, const int* in_sizes, int n_in,
                              void* d_out, int out_size)
{
    const float* x      = (const float*)d_in[0];
    const float* enc_k  = (const float*)d_in[1];
    const float* enc_v  = (const float*)d_in[2];
    const float* qkv_w  = (const float*)d_in[3];
    const float* qkv_b  = (const float*)d_in[4];
    const float* proj_w = (const float*)d_in[5];
    const float* proj_b = (const float*)d_in[6];
    float* out = (float*)d_out;
    float* loss_ptr = out + (out_size - 1);

    __nv_bfloat16 *xh, *xl, *wqh, *wql, *wph, *wpl, *oh, *ol;
    cudaGetSymbolAddress((void**)&xh,  g_xh);   cudaGetSymbolAddress((void**)&xl,  g_xl);
    cudaGetSymbolAddress((void**)&wqh, g_wqh);  cudaGetSymbolAddress((void**)&wql, g_wql);
    cudaGetSymbolAddress((void**)&wph, g_wph);  cudaGetSymbolAddress((void**)&wpl, g_wpl);
    cudaGetSymbolAddress((void**)&oh,  g_oh);   cudaGetSymbolAddress((void**)&ol,  g_ol);

    static bool attr_set = false;
    if (!attr_set) {
        cudaFuncSetAttribute(attn_kernel,
                             cudaFuncAttributeMaxDynamicSharedMemorySize, AT_SMEM_BYTES);
        cudaFuncSetAttribute(gemm_mma_kernel<0>,
                             cudaFuncAttributeMaxDynamicSharedMemorySize, GM_SMEM_BYTES);
        cudaFuncSetAttribute(gemm_mma_kernel<1>,
                             cudaFuncAttributeMaxDynamicSharedMemorySize, GM_SMEM_BYTES);
        attr_set = true;
    }

    cudaMemsetAsync(loss_ptr, 0, sizeof(float));

    // 0) fused fp32 -> bf16 hi/lo splits (all 5 tensors, one launch)
    split_all_kernel<<<(N4_ALL + 255) / 256, 256>>>(x, qkv_w, proj_w, enc_k, enc_v);

    // 1) QKV GEMM (tensor cores) -> head-major bf16 hi/lo Q(scaled)/K/V
    gemm_mma_kernel<1><<<dim3(QKVN / 128, ROWS / 128), 256, GM_SMEM_BYTES>>>(
        xh, xl, wqh, wql, qkv_b, nullptr, ROWS, QKVN, DIM);

    // 2) Dual attention + loss (256q tiles, 512 threads) -> g_oh/g_ol
    attn_kernel<<<dim3(SEQ / 256, BATCH * HEADS), 512, AT_SMEM_BYTES>>>(loss_ptr);

    // 3) proj GEMM (tensor cores) -> out
    gemm_mma_kernel<0><<<dim3(DIM / 128, ROWS / 128), 256, GM_SMEM_BYTES>>>(
        oh, ol, wph, wpl, proj_b, out, ROWS, DIM, DIM);
}